// round 13
// baseline (speedup 1.0000x reference)
#include <cuda_runtime.h>
#include <cuda_fp16.h>
#include <cstdint>

#define BSZ   16
#define LSEQ  2048
#define DDIM  256
#define MTOT  (BSZ * LSEQ)    // 32768
#define BM    128
#define BN    128
#define NTHR  256

// A (state): single fp16, 4 chunks of k64; row = 64 fp16 = 128B, SW128 phase
// baked per (l + wph). B (weights): single fp16, 4 chunks of k64, phase (n&7),
// TWO complementary-rounded variants alternated across iterations (dither).
// ext: k16 tail computing a = x@W1^T + bias exactly via hi/lo cross terms.
#define CHROW  2056
#define A_CH_ELEMS ((size_t)BSZ * CHROW * 64)   // per k64 chunk
#define W_CH   (256 * 64)

// ---------------- global state (static .bss; pad rows stay zero) ----------
__device__ __align__(128) __half g_up[2][4 * A_CH_ELEMS];
__device__ __align__(128) __half g_dn[2][4 * A_CH_ELEMS];
__device__ __align__(128) __half g_W2[2][4 * W_CH];   // [variant][chunk...]
__device__ __align__(128) __half g_W4[2][4 * W_CH];
__device__ __align__(128) __half g_xe[(size_t)MTOT * 16];
__device__ __align__(128) __half g_w2e[256 * 16];
__device__ __align__(128) __half g_w4e[256 * 16];

// ---------------- helpers ----------------
__device__ __forceinline__ uint32_t smem_u32(const void* p) {
    uint32_t a;
    asm("{ .reg .u64 t; cvta.to.shared.u64 t, %1; cvt.u32.u64 %0, t; }" : "=r"(a) : "l"(p));
    return a;
}
__device__ __forceinline__ uint32_t elect_one() {
    uint32_t pred;
    asm volatile("{\n\t.reg .pred p;\n\telect.sync _|p, 0xFFFFFFFF;\n\t"
                 "selp.b32 %0, 1, 0, p;\n\t}" : "=r"(pred));
    return pred;
}
__device__ __forceinline__ void ldm_x4(uint32_t* r, uint32_t addr) {
    asm volatile("ldmatrix.sync.aligned.m8n8.x4.shared.b16 {%0,%1,%2,%3}, [%4];"
                 : "=r"(r[0]), "=r"(r[1]), "=r"(r[2]), "=r"(r[3]) : "r"(addr));
}
__device__ __forceinline__ void mma_f16(float* c, const uint32_t* a, uint32_t b0, uint32_t b1) {
    asm volatile("mma.sync.aligned.m16n8k16.row.col.f32.f16.f16.f32 "
                 "{%0,%1,%2,%3}, {%4,%5,%6,%7}, {%8,%9}, {%0,%1,%2,%3};"
                 : "+f"(c[0]), "+f"(c[1]), "+f"(c[2]), "+f"(c[3])
                 : "r"(a[0]), "r"(a[1]), "r"(a[2]), "r"(a[3]), "r"(b0), "r"(b1));
}
__device__ __forceinline__ void bulk_g2s(uint32_t sdst, const void* gsrc,
                                         uint32_t bytes, uint32_t mbar) {
    asm volatile(
        "cp.async.bulk.shared::cluster.global.mbarrier::complete_tx::bytes [%0], [%1], %2, [%3];"
        :: "r"(sdst), "l"(gsrc), "r"(bytes), "r"(mbar) : "memory");
}
__device__ __forceinline__ void mbar_init(uint32_t mbar, uint32_t cnt) {
    asm volatile("mbarrier.init.shared.b64 [%0], %1;" :: "r"(mbar), "r"(cnt) : "memory");
}
__device__ __forceinline__ void mbar_expect_tx(uint32_t mbar, uint32_t bytes) {
    asm volatile("mbarrier.arrive.expect_tx.shared.b64 _, [%0], %1;"
                 :: "r"(mbar), "r"(bytes) : "memory");
}
__device__ __forceinline__ void mbar_arrive(uint32_t mbar) {
    asm volatile("mbarrier.arrive.release.cta.shared::cta.b64 _, [%0];"
                 :: "r"(mbar) : "memory");
}
__device__ __forceinline__ void mbar_wait(uint32_t mbar, uint32_t parity) {
    uint32_t done;
    asm volatile(
        "{\n\t.reg .pred p;\n\t"
        "mbarrier.try_wait.parity.acquire.cta.shared::cta.b64 p, [%1], %2;\n\t"
        "selp.b32 %0, 1, 0, p;\n\t}"
        : "=r"(done) : "r"(mbar), "r"(parity) : "memory");
    if (!done) {
        asm volatile(
            "{\n\t.reg .pred P1;\n\t"
            "W_%=:\n\t"
            "mbarrier.try_wait.parity.acquire.cta.shared::cta.b64 P1, [%0], %1, 0x989680;\n\t"
            "@P1 bra.uni D_%=;\n\t"
            "bra.uni W_%=;\n\t"
            "D_%=:\n\t}"
            :: "r"(mbar), "r"(parity) : "memory");
    }
}

// ---------------- SMEM layout ----------------
static constexpr int SA      = 0;
static constexpr int SB      = 16384;
static constexpr int STAGE   = 32768;
static constexpr int NSTAGE  = 3;
static constexpr int SXE     = NSTAGE * STAGE;            // 98304, A ext 4KB
static constexpr int SWE     = SXE + 4096;                // B ext 4KB
static constexpr int SM_FULL = SWE + 4096;                // 106496
static constexpr int SM_CONS = SM_FULL + NSTAGE * 8;
static constexpr int SM_EXTF = SM_CONS + NSTAGE * 8;
static constexpr int SMEM_BYTES = SM_EXTF + 8;
static constexpr uint32_t STAGE_TX = 2 * 16384;

// state element index (fp16 units) for (m, n), write-phase wph
__device__ __forceinline__ size_t st_idx(int m, int n, int wph) {
    int l = m & (LSEQ - 1);
    size_t row = (size_t)(m >> 11) * CHROW + l + 1;
    int ph  = ((l + wph) & 7) << 4;
    int raw = (n & 63) * 2;
    return (size_t)(n >> 6) * A_CH_ELEMS + row * 64 + ((raw ^ ph) >> 1);
}

// complementary fp16 rounding pair
__device__ __forceinline__ void round_pair(float w, __half& ha, __half& hb) {
    ha = __float2half(w);
    hb = __float2half(w + (w - __half2float(ha)));   // opposite-side neighbor
}

// ---------------------------------------------------------------------------
// prep: state#1 = relu(x@W1^T + b1 + b2) in fp32 -> fp16 swizzled state
// ---------------------------------------------------------------------------
__global__ void prep_kernel(const float* __restrict__ x,
                            const float* __restrict__ W1,
                            const float* __restrict__ b1,
                            const float* __restrict__ b2) {
    int idx = blockIdx.x * blockDim.x + threadIdx.x;
    if (idx >= MTOT * DDIM) return;
    int n = idx & (DDIM - 1);
    int m = idx >> 8;
    int b = m / LSEQ;
    int l = m & (LSEQ - 1);
    const float* xp = x + (size_t)b * 4 * LSEQ + l;
    float s = b1[n] + b2[n];
#pragma unroll
    for (int dd = 0; dd < 4; dd++)
        s = fmaf(xp[dd * LSEQ], W1[n * 4 + dd], s);
    __half h = __float2half(fmaxf(s, 0.0f));
    g_up[0][st_idx(m, n, +1)] = h;
    g_dn[0][st_idx(m, n, -1)] = h;
}

// build x_ext rows: [xh(4), xh(4), xl(4), 1, 1, 0, 0] per m
__global__ void xext_kernel(const float* __restrict__ x) {
    int m = blockIdx.x * blockDim.x + threadIdx.x;
    if (m >= MTOT) return;
    int b = m >> 11, l = m & (LSEQ - 1);
    __half r[16];
#pragma unroll
    for (int j = 0; j < 16; j++) r[j] = __float2half(0.0f);
#pragma unroll
    for (int dd = 0; dd < 4; dd++) {
        float xv = x[(size_t)b * 4 * LSEQ + dd * LSEQ + l];
        __half xh = __float2half(xv);
        r[dd]     = xh;
        r[4 + dd] = xh;
        r[8 + dd] = __float2half(xv - __half2float(xh));
    }
    r[12] = __float2half(1.0f);
    r[13] = __float2half(1.0f);
    uint4* dst = reinterpret_cast<uint4*>(g_xe + (size_t)m * 16);
    dst[0] = reinterpret_cast<const uint4*>(r)[0];
    dst[1] = reinterpret_cast<const uint4*>(r)[1];
}

// split W2/W4 into dithered fp16 chunk-major swizzled layout + exact ext rows
__global__ void split_w_kernel(const float* __restrict__ W2,
                               const float* __restrict__ W4,
                               const float* __restrict__ W1,
                               const float* __restrict__ b1,
                               const float* __restrict__ b2,
                               const float* __restrict__ W3,
                               const float* __restrict__ b3,
                               const float* __restrict__ b4) {
    int idx = blockIdx.x * blockDim.x + threadIdx.x;   // (n, k)
    if (idx >= DDIM * DDIM) return;
    int n = idx >> 8, k = idx & 255;
    int ph = (n & 7) << 4;
    size_t off = (size_t)(k >> 6) * W_CH + (size_t)n * 64 + ((((k & 63) * 2)) ^ ph) / 2;
    __half ha, hb;
    round_pair(W2[idx], ha, hb);
    g_W2[0][off] = ha;
    g_W2[1][off] = hb;
    round_pair(W4[idx], ha, hb);
    g_W4[0][off] = ha;
    g_W4[1][off] = hb;
    if (k == 0) {
        __half r2[16], r4[16];
#pragma unroll
        for (int j = 0; j < 16; j++) { r2[j] = __float2half(0.0f); r4[j] = r2[j]; }
#pragma unroll
        for (int dd = 0; dd < 4; dd++) {
            float w1v = W1[n * 4 + dd];
            __half w1h = __float2half(w1v);
            r2[dd]     = w1h;
            r2[4 + dd] = __float2half(w1v - __half2float(w1h));
            r2[8 + dd] = w1h;
            float w3v = W3[n * 4 + dd];
            __half w3h = __float2half(w3v);
            r4[dd]     = w3h;
            r4[4 + dd] = __float2half(w3v - __half2float(w3h));
            r4[8 + dd] = w3h;
        }
        float bias2 = b1[n] + b2[n];
        __half b2h = __float2half(bias2);
        r2[12] = b2h;
        r2[13] = __float2half(bias2 - __half2float(b2h));
        float bias4 = b3[n] + 2.0f * b4[n];
        __half b4h = __float2half(bias4);
        r4[12] = b4h;
        r4[13] = __float2half(bias4 - __half2float(b4h));
        uint4* d2 = reinterpret_cast<uint4*>(g_w2e + (size_t)n * 16);
        uint4* d4 = reinterpret_cast<uint4*>(g_w4e + (size_t)n * 16);
        d2[0] = reinterpret_cast<const uint4*>(r2)[0];
        d2[1] = reinterpret_cast<const uint4*>(r2)[1];
        d4[0] = reinterpret_cast<const uint4*>(r4)[0];
        d4[1] = reinterpret_cast<const uint4*>(r4)[1];
    }
}

// one stage = A chunk + B chunk (k64), single thread
__device__ __forceinline__ void issue_stage(uint32_t sbase, uint32_t mbar,
                                            const __half* in, const __half* w,
                                            size_t arow, int n0, int c) {
    mbar_expect_tx(mbar, STAGE_TX);
    bulk_g2s(sbase + SA, in + (size_t)c * A_CH_ELEMS + arow * 64, 16384, mbar);
    bulk_g2s(sbase + SB, w + (size_t)c * W_CH + (size_t)n0 * 64, 16384, mbar);
}
// ext pair: x rows + weight-ext rows (4KB each)
__device__ __forceinline__ void issue_ext(uint32_t sb, uint32_t mbar,
                                          const __half* we, int m0, int n0) {
    mbar_expect_tx(mbar, 8192);
    bulk_g2s(sb + SXE, g_xe + (size_t)m0 * 16, 4096, mbar);
    bulk_g2s(sb + SWE, we + (size_t)n0 * 16, 4096, mbar);
}

// compute one k64 stage, single-pass fp16. warp tile 32x64.
__device__ __forceinline__ void compute_stage(uint32_t base, int lane, int wm, int wn,
                                              float acc[2][8][4]) {
    const uint32_t swz  = (uint32_t)(lane & 7) << 4;
    const uint32_t rlo  = (uint32_t)(lane & 15);
    const uint32_t hi16 = (uint32_t)(lane >> 4) * 16;
#pragma unroll
    for (int ks = 0; ks < 4; ks++) {
        uint32_t ch = ((uint32_t)(ks * 32) + hi16) ^ swz;
        uint32_t ah[2][4];
#pragma unroll
        for (int mt = 0; mt < 2; mt++)
            ldm_x4(ah[mt], base + SA + (wm * 32 + mt * 16 + rlo) * 128 + ch);
        uint32_t bf[4][4];
#pragma unroll
        for (int pr = 0; pr < 4; pr++)
            ldm_x4(bf[pr], base + SB + ((wn * 4 + pr) * 16 + rlo) * 128 + ch);
#pragma unroll
        for (int pr = 0; pr < 4; pr++)
#pragma unroll
            for (int mt = 0; mt < 2; mt++) {
                mma_f16(acc[mt][pr * 2],     ah[mt], bf[pr][0], bf[pr][2]);
                mma_f16(acc[mt][pr * 2 + 1], ah[mt], bf[pr][1], bf[pr][3]);
            }
    }
}

// ext k16 step: rows of 32B, unswizzled
__device__ __forceinline__ void compute_ext(uint32_t sb, int lane, int wm, int wn,
                                            float acc[2][8][4]) {
    const uint32_t rlo  = (uint32_t)(lane & 15);
    const uint32_t hi16 = (uint32_t)(lane >> 4) * 16;
    uint32_t ah[2][4];
#pragma unroll
    for (int mt = 0; mt < 2; mt++)
        ldm_x4(ah[mt], sb + SXE + (wm * 32 + mt * 16 + rlo) * 32 + hi16);
    uint32_t bf[4][4];
#pragma unroll
    for (int pr = 0; pr < 4; pr++)
        ldm_x4(bf[pr], sb + SWE + ((wn * 4 + pr) * 16 + rlo) * 32 + hi16);
#pragma unroll
    for (int pr = 0; pr < 4; pr++)
#pragma unroll
        for (int mt = 0; mt < 2; mt++) {
            mma_f16(acc[mt][pr * 2],     ah[mt], bf[pr][0], bf[pr][2]);
            mma_f16(acc[mt][pr * 2 + 1], ah[mt], bf[pr][1], bf[pr][3]);
        }
}

// ---------------------------------------------------------------------------
// DP iteration: out = relu(shift(in)@W2^T + x@W1^T + b1 + b2), dithered W2.
// ---------------------------------------------------------------------------
__global__ __launch_bounds__(NTHR, 2) void dp_iter_kernel(int src, int wvar) {
    extern __shared__ char smem[];
    const uint32_t sb = smem_u32(smem);
    const int tid = threadIdx.x, lane = tid & 31, wid = tid >> 5;
    const int wm = wid >> 1, wn = wid & 1;
    const int m0 = blockIdx.x * BM;
    const int n0 = blockIdx.y * BN;
    const int ln = blockIdx.z;

    const __half* in  = ln ? g_dn[src]     : g_up[src];
    __half*       out = ln ? g_dn[src ^ 1] : g_up[src ^ 1];
    const __half* w2  = g_W2[wvar];
    const int shift = ln ? 1 : -1;
    const int wph = -shift;
    const size_t arow = (size_t)(m0 >> 11) * CHROW + (m0 & (LSEQ - 1)) + 1 + shift;

    if (tid == 0) {
        for (int s = 0; s < NSTAGE; s++) {
            mbar_init(sb + SM_FULL + s * 8, 1);
            mbar_init(sb + SM_CONS + s * 8, 8);
        }
        mbar_init(sb + SM_EXTF, 1);
    }
    __syncthreads();
    if (tid == 0) {
        issue_ext(sb, sb + SM_EXTF, g_w2e, m0, n0);
        for (int s = 0; s < NSTAGE; s++)
            issue_stage(sb + s * STAGE, sb + SM_FULL + s * 8, in, w2, arow, n0, s);
    }

    float acc[2][8][4];
#pragma unroll
    for (int i = 0; i < 2; i++)
#pragma unroll
        for (int j = 0; j < 8; j++)
#pragma unroll
            for (int q = 0; q < 4; q++) acc[i][j][q] = 0.0f;

    const bool prod = (wid == 0) && elect_one();
    int buf = 0, par = 0;
#pragma unroll 1
    for (int c = 0; c < 4; c++) {
        mbar_wait(sb + SM_FULL + buf * 8, par);
        compute_stage(sb + buf * STAGE, lane, wm, wn, acc);
        if (elect_one()) mbar_arrive(sb + SM_CONS + buf * 8);
        if (c < 1 && prod) {
            mbar_wait(sb + SM_CONS + buf * 8, par);
            issue_stage(sb + buf * STAGE, sb + SM_FULL + buf * 8, in, w2, arow, n0, c + 3);
        }
        if (++buf == NSTAGE) { buf = 0; par ^= 1; }
    }
    mbar_wait(sb + SM_EXTF, 0);
    compute_ext(sb, lane, wm, wn, acc);

    // epilogue: relu(acc) -> fp16 state, swizzled layout (no global reads)
#pragma unroll
    for (int mt = 0; mt < 2; mt++) {
#pragma unroll
        for (int h = 0; h < 2; h++) {
            int m = m0 + wm * 32 + mt * 16 + (lane >> 2) + h * 8;
            int l = m & (LSEQ - 1);
            size_t rowbase = ((size_t)(m >> 11) * CHROW + l + 1) * 64;
            int ph = ((l + wph) & 7) << 4;
#pragma unroll
            for (int nt = 0; nt < 8; nt++) {
                int n = n0 + wn * 64 + nt * 8 + (lane & 3) * 2;
                __half2 hv;
                hv.x = __float2half(fmaxf(acc[mt][nt][2 * h],     0.0f));
                hv.y = __float2half(fmaxf(acc[mt][nt][2 * h + 1], 0.0f));
                size_t off = (size_t)(n >> 6) * A_CH_ELEMS + rowbase
                           + ((((n & 63) * 2) ^ ph) >> 1);
                *reinterpret_cast<__half2*>(out + off) = hv;
            }
        }
    }
}

// ---------------------------------------------------------------------------
// final: miu = relu(x@W3^T + b3 + 2*b4 + W4a*up[j-1] + W4b*down[j+1])
// 8 stages (up uses W4 variant 0, down variant 1) + ext. grid (m_tiles, 2).
// ---------------------------------------------------------------------------
__global__ __launch_bounds__(NTHR, 2) void final_kernel(float* __restrict__ out,
                                                        int src) {
    extern __shared__ char smem[];
    const uint32_t sb = smem_u32(smem);
    const int tid = threadIdx.x, lane = tid & 31, wid = tid >> 5;
    const int wm = wid >> 1, wn = wid & 1;
    const int m0 = blockIdx.x * BM;
    const int n0 = blockIdx.y * BN;
    const size_t rbase = (size_t)(m0 >> 11) * CHROW + (m0 & (LSEQ - 1)) + 1;
    const size_t arow_up = rbase - 1;
    const size_t arow_dn = rbase + 1;
    const __half* upp = g_up[src];
    const __half* dnp = g_dn[src];

    if (tid == 0) {
        for (int s = 0; s < NSTAGE; s++) {
            mbar_init(sb + SM_FULL + s * 8, 1);
            mbar_init(sb + SM_CONS + s * 8, 8);
        }
        mbar_init(sb + SM_EXTF, 1);
    }
    __syncthreads();
    if (tid == 0) {
        issue_ext(sb, sb + SM_EXTF, g_w4e, m0, n0);
        for (int s = 0; s < NSTAGE; s++)
            issue_stage(sb + s * STAGE, sb + SM_FULL + s * 8, upp, g_W4[0],
                        arow_up, n0, s);
    }

    float acc[2][8][4];
#pragma unroll
    for (int i = 0; i < 2; i++)
#pragma unroll
        for (int j = 0; j < 8; j++)
#pragma unroll
            for (int q = 0; q < 4; q++) acc[i][j][q] = 0.0f;

    const bool prod = (wid == 0) && elect_one();
    int buf = 0, par = 0;
#pragma unroll 1
    for (int t = 0; t < 8; t++) {
        mbar_wait(sb + SM_FULL + buf * 8, par);
        compute_stage(sb + buf * STAGE, lane, wm, wn, acc);
        if (elect_one()) mbar_arrive(sb + SM_CONS + buf * 8);
        if (t < 5 && prod) {
            mbar_wait(sb + SM_CONS + buf * 8, par);
            int tn = t + 3;
            int phx = tn >> 2;
            issue_stage(sb + buf * STAGE, sb + SM_FULL + buf * 8,
                        phx ? dnp : upp, g_W4[phx],
                        phx ? arow_dn : arow_up, n0, tn & 3);
        }
        if (++buf == NSTAGE) { buf = 0; par ^= 1; }
    }
    mbar_wait(sb + SM_EXTF, 0);
    compute_ext(sb, lane, wm, wn, acc);

    // epilogue: relu(acc) -> fp32 out (linear layout)
#pragma unroll
    for (int mt = 0; mt < 2; mt++) {
#pragma unroll
        for (int h = 0; h < 2; h++) {
            int m = m0 + wm * 32 + mt * 16 + (lane >> 2) + h * 8;
            float* orow = out + (size_t)m * DDIM;
#pragma unroll
            for (int nt = 0; nt < 8; nt++) {
                int n = n0 + wn * 64 + nt * 8 + (lane & 3) * 2;
                float2 o = make_float2(fmaxf(acc[mt][nt][2 * h],     0.0f),
                                       fmaxf(acc[mt][nt][2 * h + 1], 0.0f));
                *reinterpret_cast<float2*>(orow + n) = o;
            }
        }
    }
}

// ---------------------------------------------------------------------------
extern "C" void kernel_launch(void* const* d_in, const int* in_sizes, int n_in,
                              void* d_out, int out_size) {
    const float* x  = (const float*)d_in[0];
    const float* W1 = (const float*)d_in[1];
    const float* b1 = (const float*)d_in[2];
    const float* W2 = (const float*)d_in[3];
    const float* b2 = (const float*)d_in[4];
    const float* W3 = (const float*)d_in[5];
    const float* b3 = (const float*)d_in[6];
    const float* W4 = (const float*)d_in[7];
    const float* b4 = (const float*)d_in[8];
    float* out = (float*)d_out;

    cudaFuncSetAttribute(dp_iter_kernel, cudaFuncAttributeMaxDynamicSharedMemorySize, SMEM_BYTES);
    cudaFuncSetAttribute(final_kernel,   cudaFuncAttributeMaxDynamicSharedMemorySize, SMEM_BYTES);

    int total = MTOT * DDIM;
    prep_kernel<<<(total + 255) / 256, 256>>>(x, W1, b1, b2);
    xext_kernel<<<(MTOT + 255) / 256, 256>>>(x);
    split_w_kernel<<<(DDIM * DDIM + 255) / 256, 256>>>(W2, W4, W1, b1, b2, W3, b3, b4);

    int src = 0;
    for (int t = 0; t < 7; t++) {
        dp_iter_kernel<<<dim3(MTOT / BM, 2, 2), NTHR, SMEM_BYTES>>>(src, t & 1);
        src ^= 1;
    }
    final_kernel<<<dim3(MTOT / BM, 2), NTHR, SMEM_BYTES>>>(out, src);
}

// round 14
// speedup vs baseline: 1.4861x; 1.4861x over previous
#include <cuda_runtime.h>
#include <cuda_fp16.h>
#include <cstdint>

#define BSZ   16
#define LSEQ  2048
#define DDIM  256
#define MTOT  (BSZ * LSEQ)    // 32768
#define BM    128
#define BN    128
#define NTHR  256

// A (state): single fp16, 4 chunks of k64; row = 64 fp16 = 128B, SW128 phase
// baked per (l + wph). B (weights): single fp16, 4 chunks of k64, phase (n&7),
// TWO complementary-rounded variants alternated across iterations (dither).
// ext: k16 tail computing a = x@W1^T + bias exactly via hi/lo cross terms.
#define CHROW  2056
#define A_CH_ELEMS ((size_t)BSZ * CHROW * 64)   // per k64 chunk
#define W_CH   (256 * 64)

// ---------------- global state (static .bss; pad rows stay zero) ----------
__device__ __align__(128) __half g_up[2][4 * A_CH_ELEMS];
__device__ __align__(128) __half g_dn[2][4 * A_CH_ELEMS];
__device__ __align__(128) __half g_W2[2][4 * W_CH];   // [variant][chunk...]
__device__ __align__(128) __half g_W4[2][4 * W_CH];
__device__ __align__(128) __half g_xe[(size_t)MTOT * 16];
__device__ __align__(128) __half g_w2e[256 * 16];
__device__ __align__(128) __half g_w4e[256 * 16];

// ---------------- helpers ----------------
__device__ __forceinline__ uint32_t smem_u32(const void* p) {
    uint32_t a;
    asm("{ .reg .u64 t; cvta.to.shared.u64 t, %1; cvt.u32.u64 %0, t; }" : "=r"(a) : "l"(p));
    return a;
}
__device__ __forceinline__ uint32_t elect_one() {
    uint32_t pred;
    asm volatile("{\n\t.reg .pred p;\n\telect.sync _|p, 0xFFFFFFFF;\n\t"
                 "selp.b32 %0, 1, 0, p;\n\t}" : "=r"(pred));
    return pred;
}
__device__ __forceinline__ void ldm_x4(uint32_t* r, uint32_t addr) {
    asm volatile("ldmatrix.sync.aligned.m8n8.x4.shared.b16 {%0,%1,%2,%3}, [%4];"
                 : "=r"(r[0]), "=r"(r[1]), "=r"(r[2]), "=r"(r[3]) : "r"(addr));
}
__device__ __forceinline__ void mma_f16(float* c, const uint32_t* a, uint32_t b0, uint32_t b1) {
    asm volatile("mma.sync.aligned.m16n8k16.row.col.f32.f16.f16.f32 "
                 "{%0,%1,%2,%3}, {%4,%5,%6,%7}, {%8,%9}, {%0,%1,%2,%3};"
                 : "+f"(c[0]), "+f"(c[1]), "+f"(c[2]), "+f"(c[3])
                 : "r"(a[0]), "r"(a[1]), "r"(a[2]), "r"(a[3]), "r"(b0), "r"(b1));
}
__device__ __forceinline__ void bulk_g2s(uint32_t sdst, const void* gsrc,
                                         uint32_t bytes, uint32_t mbar) {
    asm volatile(
        "cp.async.bulk.shared::cluster.global.mbarrier::complete_tx::bytes [%0], [%1], %2, [%3];"
        :: "r"(sdst), "l"(gsrc), "r"(bytes), "r"(mbar) : "memory");
}
__device__ __forceinline__ void mbar_init(uint32_t mbar, uint32_t cnt) {
    asm volatile("mbarrier.init.shared.b64 [%0], %1;" :: "r"(mbar), "r"(cnt) : "memory");
}
__device__ __forceinline__ void mbar_expect_tx(uint32_t mbar, uint32_t bytes) {
    asm volatile("mbarrier.arrive.expect_tx.shared.b64 _, [%0], %1;"
                 :: "r"(mbar), "r"(bytes) : "memory");
}
__device__ __forceinline__ void mbar_arrive(uint32_t mbar) {
    asm volatile("mbarrier.arrive.release.cta.shared::cta.b64 _, [%0];"
                 :: "r"(mbar) : "memory");
}
__device__ __forceinline__ void mbar_wait(uint32_t mbar, uint32_t parity) {
    uint32_t done;
    asm volatile(
        "{\n\t.reg .pred p;\n\t"
        "mbarrier.try_wait.parity.acquire.cta.shared::cta.b64 p, [%1], %2;\n\t"
        "selp.b32 %0, 1, 0, p;\n\t}"
        : "=r"(done) : "r"(mbar), "r"(parity) : "memory");
    if (!done) {
        asm volatile(
            "{\n\t.reg .pred P1;\n\t"
            "W_%=:\n\t"
            "mbarrier.try_wait.parity.acquire.cta.shared::cta.b64 P1, [%0], %1, 0x989680;\n\t"
            "@P1 bra.uni D_%=;\n\t"
            "bra.uni W_%=;\n\t"
            "D_%=:\n\t}"
            :: "r"(mbar), "r"(parity) : "memory");
    }
}

// ---------------- SMEM layout ----------------
static constexpr int SA      = 0;
static constexpr int SB      = 16384;
static constexpr int STAGE   = 32768;
static constexpr int NSTAGE  = 3;
static constexpr int SXE     = NSTAGE * STAGE;            // 98304, A ext 4KB
static constexpr int SWE     = SXE + 4096;                // B ext 4KB
static constexpr int SM_FULL = SWE + 4096;                // 106496
static constexpr int SM_CONS = SM_FULL + NSTAGE * 8;
static constexpr int SM_EXTF = SM_CONS + NSTAGE * 8;
static constexpr int SMEM_BYTES = SM_EXTF + 8;
static constexpr uint32_t STAGE_TX = 2 * 16384;

// state element index (fp16 units) for (m, n), write-phase wph
__device__ __forceinline__ size_t st_idx(int m, int n, int wph) {
    int l = m & (LSEQ - 1);
    size_t row = (size_t)(m >> 11) * CHROW + l + 1;
    int ph  = ((l + wph) & 7) << 4;
    int raw = (n & 63) * 2;
    return (size_t)(n >> 6) * A_CH_ELEMS + row * 64 + ((raw ^ ph) >> 1);
}

// complementary fp16 rounding pair
__device__ __forceinline__ void round_pair(float w, __half& ha, __half& hb) {
    ha = __float2half(w);
    hb = __float2half(w + (w - __half2float(ha)));   // opposite-side neighbor
}

// ---------------------------------------------------------------------------
// prep: state#1 = relu(x@W1^T + b1 + b2) in fp32 -> fp16 swizzled state.
// Each thread computes TWO adjacent n (even n) -> half2 stores.
// ---------------------------------------------------------------------------
__global__ void prep_kernel(const float* __restrict__ x,
                            const float* __restrict__ W1,
                            const float* __restrict__ b1,
                            const float* __restrict__ b2) {
    int idx = blockIdx.x * blockDim.x + threadIdx.x;
    if (idx >= MTOT * (DDIM / 2)) return;
    int n = (idx & 127) * 2;
    int m = idx >> 7;
    int b = m / LSEQ;
    int l = m & (LSEQ - 1);
    const float* xp = x + (size_t)b * 4 * LSEQ + l;
    float xv[4];
#pragma unroll
    for (int dd = 0; dd < 4; dd++) xv[dd] = xp[dd * LSEQ];
    float s0 = b1[n]     + b2[n];
    float s1 = b1[n + 1] + b2[n + 1];
#pragma unroll
    for (int dd = 0; dd < 4; dd++) {
        s0 = fmaf(xv[dd], W1[n * 4 + dd],       s0);
        s1 = fmaf(xv[dd], W1[(n + 1) * 4 + dd], s1);
    }
    __half2 hv;
    hv.x = __float2half(fmaxf(s0, 0.0f));
    hv.y = __float2half(fmaxf(s1, 0.0f));
    *reinterpret_cast<__half2*>(&g_up[0][st_idx(m, n, +1)]) = hv;
    *reinterpret_cast<__half2*>(&g_dn[0][st_idx(m, n, -1)]) = hv;
}

// build x_ext rows: [xh(4), xh(4), xl(4), 1, 1, 0, 0] per m
__global__ void xext_kernel(const float* __restrict__ x) {
    int m = blockIdx.x * blockDim.x + threadIdx.x;
    if (m >= MTOT) return;
    int b = m >> 11, l = m & (LSEQ - 1);
    __half r[16];
#pragma unroll
    for (int j = 0; j < 16; j++) r[j] = __float2half(0.0f);
#pragma unroll
    for (int dd = 0; dd < 4; dd++) {
        float xv = x[(size_t)b * 4 * LSEQ + dd * LSEQ + l];
        __half xh = __float2half(xv);
        r[dd]     = xh;
        r[4 + dd] = xh;
        r[8 + dd] = __float2half(xv - __half2float(xh));
    }
    r[12] = __float2half(1.0f);
    r[13] = __float2half(1.0f);
    uint4* dst = reinterpret_cast<uint4*>(g_xe + (size_t)m * 16);
    dst[0] = reinterpret_cast<const uint4*>(r)[0];
    dst[1] = reinterpret_cast<const uint4*>(r)[1];
}

// split W2/W4 into dithered fp16 chunk-major swizzled layout + exact ext rows
__global__ void split_w_kernel(const float* __restrict__ W2,
                               const float* __restrict__ W4,
                               const float* __restrict__ W1,
                               const float* __restrict__ b1,
                               const float* __restrict__ b2,
                               const float* __restrict__ W3,
                               const float* __restrict__ b3,
                               const float* __restrict__ b4) {
    int idx = blockIdx.x * blockDim.x + threadIdx.x;   // (n, k)
    if (idx >= DDIM * DDIM) return;
    int n = idx >> 8, k = idx & 255;
    int ph = (n & 7) << 4;
    size_t off = (size_t)(k >> 6) * W_CH + (size_t)n * 64 + ((((k & 63) * 2)) ^ ph) / 2;
    __half ha, hb;
    round_pair(W2[idx], ha, hb);
    g_W2[0][off] = ha;
    g_W2[1][off] = hb;
    round_pair(W4[idx], ha, hb);
    g_W4[0][off] = ha;
    g_W4[1][off] = hb;
    if (k == 0) {
        __half r2[16], r4[16];
#pragma unroll
        for (int j = 0; j < 16; j++) { r2[j] = __float2half(0.0f); r4[j] = r2[j]; }
#pragma unroll
        for (int dd = 0; dd < 4; dd++) {
            float w1v = W1[n * 4 + dd];
            __half w1h = __float2half(w1v);
            r2[dd]     = w1h;
            r2[4 + dd] = __float2half(w1v - __half2float(w1h));
            r2[8 + dd] = w1h;
            float w3v = W3[n * 4 + dd];
            __half w3h = __float2half(w3v);
            r4[dd]     = w3h;
            r4[4 + dd] = __float2half(w3v - __half2float(w3h));
            r4[8 + dd] = w3h;
        }
        float bias2 = b1[n] + b2[n];
        __half b2h = __float2half(bias2);
        r2[12] = b2h;
        r2[13] = __float2half(bias2 - __half2float(b2h));
        float bias4 = b3[n] + 2.0f * b4[n];
        __half b4h = __float2half(bias4);
        r4[12] = b4h;
        r4[13] = __float2half(bias4 - __half2float(b4h));
        uint4* d2 = reinterpret_cast<uint4*>(g_w2e + (size_t)n * 16);
        uint4* d4 = reinterpret_cast<uint4*>(g_w4e + (size_t)n * 16);
        d2[0] = reinterpret_cast<const uint4*>(r2)[0];
        d2[1] = reinterpret_cast<const uint4*>(r2)[1];
        d4[0] = reinterpret_cast<const uint4*>(r4)[0];
        d4[1] = reinterpret_cast<const uint4*>(r4)[1];
    }
}

// one stage = A chunk + B chunk (k64), single thread
__device__ __forceinline__ void issue_stage(uint32_t sbase, uint32_t mbar,
                                            const __half* in, const __half* w,
                                            size_t arow, int n0, int c) {
    mbar_expect_tx(mbar, STAGE_TX);
    bulk_g2s(sbase + SA, in + (size_t)c * A_CH_ELEMS + arow * 64, 16384, mbar);
    bulk_g2s(sbase + SB, w + (size_t)c * W_CH + (size_t)n0 * 64, 16384, mbar);
}
// ext pair: x rows + weight-ext rows (4KB each)
__device__ __forceinline__ void issue_ext(uint32_t sb, uint32_t mbar,
                                          const __half* we, int m0, int n0) {
    mbar_expect_tx(mbar, 8192);
    bulk_g2s(sb + SXE, g_xe + (size_t)m0 * 16, 4096, mbar);
    bulk_g2s(sb + SWE, we + (size_t)n0 * 16, 4096, mbar);
}

// compute one k64 stage, single-pass fp16. warp tile 32x64.
__device__ __forceinline__ void compute_stage(uint32_t base, int lane, int wm, int wn,
                                              float acc[2][8][4]) {
    const uint32_t swz  = (uint32_t)(lane & 7) << 4;
    const uint32_t rlo  = (uint32_t)(lane & 15);
    const uint32_t hi16 = (uint32_t)(lane >> 4) * 16;
#pragma unroll
    for (int ks = 0; ks < 4; ks++) {
        uint32_t ch = ((uint32_t)(ks * 32) + hi16) ^ swz;
        uint32_t ah[2][4];
#pragma unroll
        for (int mt = 0; mt < 2; mt++)
            ldm_x4(ah[mt], base + SA + (wm * 32 + mt * 16 + rlo) * 128 + ch);
        uint32_t bf[4][4];
#pragma unroll
        for (int pr = 0; pr < 4; pr++)
            ldm_x4(bf[pr], base + SB + ((wn * 4 + pr) * 16 + rlo) * 128 + ch);
#pragma unroll
        for (int pr = 0; pr < 4; pr++)
#pragma unroll
            for (int mt = 0; mt < 2; mt++) {
                mma_f16(acc[mt][pr * 2],     ah[mt], bf[pr][0], bf[pr][2]);
                mma_f16(acc[mt][pr * 2 + 1], ah[mt], bf[pr][1], bf[pr][3]);
            }
    }
}

// ext k16 step: rows of 32B, unswizzled
__device__ __forceinline__ void compute_ext(uint32_t sb, int lane, int wm, int wn,
                                            float acc[2][8][4]) {
    const uint32_t rlo  = (uint32_t)(lane & 15);
    const uint32_t hi16 = (uint32_t)(lane >> 4) * 16;
    uint32_t ah[2][4];
#pragma unroll
    for (int mt = 0; mt < 2; mt++)
        ldm_x4(ah[mt], sb + SXE + (wm * 32 + mt * 16 + rlo) * 32 + hi16);
    uint32_t bf[4][4];
#pragma unroll
    for (int pr = 0; pr < 4; pr++)
        ldm_x4(bf[pr], sb + SWE + ((wn * 4 + pr) * 16 + rlo) * 32 + hi16);
#pragma unroll
    for (int pr = 0; pr < 4; pr++)
#pragma unroll
        for (int mt = 0; mt < 2; mt++) {
            mma_f16(acc[mt][pr * 2],     ah[mt], bf[pr][0], bf[pr][2]);
            mma_f16(acc[mt][pr * 2 + 1], ah[mt], bf[pr][1], bf[pr][3]);
        }
}

// ---------------------------------------------------------------------------
// DP iteration: out = relu(shift(in)@W2^T + x@W1^T + b1 + b2), dithered W2.
// ---------------------------------------------------------------------------
__global__ __launch_bounds__(NTHR, 2) void dp_iter_kernel(int src, int wvar) {
    extern __shared__ char smem[];
    const uint32_t sb = smem_u32(smem);
    const int tid = threadIdx.x, lane = tid & 31, wid = tid >> 5;
    const int wm = wid >> 1, wn = wid & 1;
    const int m0 = blockIdx.x * BM;
    const int n0 = blockIdx.y * BN;
    const int ln = blockIdx.z;

    const __half* in  = ln ? g_dn[src]     : g_up[src];
    __half*       out = ln ? g_dn[src ^ 1] : g_up[src ^ 1];
    const __half* w2  = g_W2[wvar];
    const int shift = ln ? 1 : -1;
    const int wph = -shift;
    const size_t arow = (size_t)(m0 >> 11) * CHROW + (m0 & (LSEQ - 1)) + 1 + shift;

    if (tid == 0) {
        for (int s = 0; s < NSTAGE; s++) {
            mbar_init(sb + SM_FULL + s * 8, 1);
            mbar_init(sb + SM_CONS + s * 8, 8);
        }
        mbar_init(sb + SM_EXTF, 1);
    }
    __syncthreads();
    if (tid == 0) {
        issue_ext(sb, sb + SM_EXTF, g_w2e, m0, n0);
        for (int s = 0; s < NSTAGE; s++)
            issue_stage(sb + s * STAGE, sb + SM_FULL + s * 8, in, w2, arow, n0, s);
    }

    float acc[2][8][4];
#pragma unroll
    for (int i = 0; i < 2; i++)
#pragma unroll
        for (int j = 0; j < 8; j++)
#pragma unroll
            for (int q = 0; q < 4; q++) acc[i][j][q] = 0.0f;

    const bool prod = (wid == 0) && elect_one();
    int buf = 0, par = 0;
#pragma unroll 1
    for (int c = 0; c < 4; c++) {
        mbar_wait(sb + SM_FULL + buf * 8, par);
        compute_stage(sb + buf * STAGE, lane, wm, wn, acc);
        if (c == 0) {      // only buffer 0 is ever refilled (stage 3)
            if (elect_one()) mbar_arrive(sb + SM_CONS + buf * 8);
            if (prod) {
                mbar_wait(sb + SM_CONS + buf * 8, par);
                issue_stage(sb + buf * STAGE, sb + SM_FULL + buf * 8, in, w2, arow, n0, 3);
            }
        }
        if (++buf == NSTAGE) { buf = 0; par ^= 1; }
    }
    mbar_wait(sb + SM_EXTF, 0);
    compute_ext(sb, lane, wm, wn, acc);

    // epilogue: relu(acc) -> fp16 state, swizzled layout (no global reads)
#pragma unroll
    for (int mt = 0; mt < 2; mt++) {
#pragma unroll
        for (int h = 0; h < 2; h++) {
            int m = m0 + wm * 32 + mt * 16 + (lane >> 2) + h * 8;
            int l = m & (LSEQ - 1);
            size_t rowbase = ((size_t)(m >> 11) * CHROW + l + 1) * 64;
            int ph = ((l + wph) & 7) << 4;
#pragma unroll
            for (int nt = 0; nt < 8; nt++) {
                int n = n0 + wn * 64 + nt * 8 + (lane & 3) * 2;
                __half2 hv;
                hv.x = __float2half(fmaxf(acc[mt][nt][2 * h],     0.0f));
                hv.y = __float2half(fmaxf(acc[mt][nt][2 * h + 1], 0.0f));
                size_t off = (size_t)(n >> 6) * A_CH_ELEMS + rowbase
                           + ((((n & 63) * 2) ^ ph) >> 1);
                *reinterpret_cast<__half2*>(out + off) = hv;
            }
        }
    }
}

// ---------------------------------------------------------------------------
// final: miu = relu(x@W3^T + b3 + 2*b4 + W4a*up[j-1] + W4b*down[j+1])
// 8 stages (up uses W4 variant 0, down variant 1) + ext. grid (m_tiles, 2).
// ---------------------------------------------------------------------------
__global__ __launch_bounds__(NTHR, 2) void final_kernel(float* __restrict__ out,
                                                        int src) {
    extern __shared__ char smem[];
    const uint32_t sb = smem_u32(smem);
    const int tid = threadIdx.x, lane = tid & 31, wid = tid >> 5;
    const int wm = wid >> 1, wn = wid & 1;
    const int m0 = blockIdx.x * BM;
    const int n0 = blockIdx.y * BN;
    const size_t rbase = (size_t)(m0 >> 11) * CHROW + (m0 & (LSEQ - 1)) + 1;
    const size_t arow_up = rbase - 1;
    const size_t arow_dn = rbase + 1;
    const __half* upp = g_up[src];
    const __half* dnp = g_dn[src];

    if (tid == 0) {
        for (int s = 0; s < NSTAGE; s++) {
            mbar_init(sb + SM_FULL + s * 8, 1);
            mbar_init(sb + SM_CONS + s * 8, 8);
        }
        mbar_init(sb + SM_EXTF, 1);
    }
    __syncthreads();
    if (tid == 0) {
        issue_ext(sb, sb + SM_EXTF, g_w4e, m0, n0);
        for (int s = 0; s < NSTAGE; s++)
            issue_stage(sb + s * STAGE, sb + SM_FULL + s * 8, upp, g_W4[0],
                        arow_up, n0, s);
    }

    float acc[2][8][4];
#pragma unroll
    for (int i = 0; i < 2; i++)
#pragma unroll
        for (int j = 0; j < 8; j++)
#pragma unroll
            for (int q = 0; q < 4; q++) acc[i][j][q] = 0.0f;

    const bool prod = (wid == 0) && elect_one();
    int buf = 0, par = 0;
#pragma unroll 1
    for (int t = 0; t < 8; t++) {
        mbar_wait(sb + SM_FULL + buf * 8, par);
        compute_stage(sb + buf * STAGE, lane, wm, wn, acc);
        if (t < 5) {
            if (elect_one()) mbar_arrive(sb + SM_CONS + buf * 8);
            if (prod) {
                mbar_wait(sb + SM_CONS + buf * 8, par);
                int tn = t + 3;
                int phx = tn >> 2;
                issue_stage(sb + buf * STAGE, sb + SM_FULL + buf * 8,
                            phx ? dnp : upp, g_W4[phx],
                            phx ? arow_dn : arow_up, n0, tn & 3);
            }
        }
        if (++buf == NSTAGE) { buf = 0; par ^= 1; }
    }
    mbar_wait(sb + SM_EXTF, 0);
    compute_ext(sb, lane, wm, wn, acc);

    // epilogue: relu(acc) -> fp32 out (linear layout)
#pragma unroll
    for (int mt = 0; mt < 2; mt++) {
#pragma unroll
        for (int h = 0; h < 2; h++) {
            int m = m0 + wm * 32 + mt * 16 + (lane >> 2) + h * 8;
            float* orow = out + (size_t)m * DDIM;
#pragma unroll
            for (int nt = 0; nt < 8; nt++) {
                int n = n0 + wn * 64 + nt * 8 + (lane & 3) * 2;
                float2 o = make_float2(fmaxf(acc[mt][nt][2 * h],     0.0f),
                                       fmaxf(acc[mt][nt][2 * h + 1], 0.0f));
                *reinterpret_cast<float2*>(orow + n) = o;
            }
        }
    }
}

// ---------------------------------------------------------------------------
extern "C" void kernel_launch(void* const* d_in, const int* in_sizes, int n_in,
                              void* d_out, int out_size) {
    const float* x  = (const float*)d_in[0];
    const float* W1 = (const float*)d_in[1];
    const float* b1 = (const float*)d_in[2];
    const float* W2 = (const float*)d_in[3];
    const float* b2 = (const float*)d_in[4];
    const float* W3 = (const float*)d_in[5];
    const float* b3 = (const float*)d_in[6];
    const float* W4 = (const float*)d_in[7];
    const float* b4 = (const float*)d_in[8];
    float* out = (float*)d_out;

    cudaFuncSetAttribute(dp_iter_kernel, cudaFuncAttributeMaxDynamicSharedMemorySize, SMEM_BYTES);
    cudaFuncSetAttribute(final_kernel,   cudaFuncAttributeMaxDynamicSharedMemorySize, SMEM_BYTES);

    prep_kernel<<<(MTOT * (DDIM / 2) + 255) / 256, 256>>>(x, W1, b1, b2);
    xext_kernel<<<(MTOT + 255) / 256, 256>>>(x);
    split_w_kernel<<<(DDIM * DDIM + 255) / 256, 256>>>(W2, W4, W1, b1, b2, W3, b3, b4);

    int src = 0;
    for (int t = 0; t < 7; t++) {
        dp_iter_kernel<<<dim3(MTOT / BM, 2, 2), NTHR, SMEM_BYTES>>>(src, t & 1);
        src ^= 1;
    }
    final_kernel<<<dim3(MTOT / BM, 2), NTHR, SMEM_BYTES>>>(out, src);
}

// round 15
// speedup vs baseline: 1.5463x; 1.0405x over previous
#include <cuda_runtime.h>
#include <cuda_fp16.h>
#include <cstdint>

#define BSZ   16
#define LSEQ  2048
#define DDIM  256
#define MTOT  (BSZ * LSEQ)    // 32768
#define BM    128
#define BN    128
#define NTHR  256

// A (state): single fp16, 4 chunks of k64; row = 64 fp16 = 128B, SW128 phase
// baked per (l + wph). B (weights): single fp16, 4 chunks of k64, phase (n&7),
// TWO complementary-rounded variants alternated across iterations (dither).
// ext: k16 tail computing a = x@W1^T + bias exactly via hi/lo cross terms.
// PDL: weight-side prefetch issued before cudaGridDependencySynchronize so it
// overlaps the predecessor kernel's tail; state-side (A) prefetch after.
#define CHROW  2056
#define A_CH_ELEMS ((size_t)BSZ * CHROW * 64)   // per k64 chunk
#define W_CH   (256 * 64)

// ---------------- global state (static .bss; pad rows stay zero) ----------
__device__ __align__(128) __half g_up[2][4 * A_CH_ELEMS];
__device__ __align__(128) __half g_dn[2][4 * A_CH_ELEMS];
__device__ __align__(128) __half g_W2[2][4 * W_CH];   // [variant][chunk...]
__device__ __align__(128) __half g_W4[2][4 * W_CH];
__device__ __align__(128) __half g_xe[(size_t)MTOT * 16];
__device__ __align__(128) __half g_w2e[256 * 16];
__device__ __align__(128) __half g_w4e[256 * 16];

// ---------------- helpers ----------------
__device__ __forceinline__ uint32_t smem_u32(const void* p) {
    uint32_t a;
    asm("{ .reg .u64 t; cvta.to.shared.u64 t, %1; cvt.u32.u64 %0, t; }" : "=r"(a) : "l"(p));
    return a;
}
__device__ __forceinline__ uint32_t elect_one() {
    uint32_t pred;
    asm volatile("{\n\t.reg .pred p;\n\telect.sync _|p, 0xFFFFFFFF;\n\t"
                 "selp.b32 %0, 1, 0, p;\n\t}" : "=r"(pred));
    return pred;
}
__device__ __forceinline__ void ldm_x4(uint32_t* r, uint32_t addr) {
    asm volatile("ldmatrix.sync.aligned.m8n8.x4.shared.b16 {%0,%1,%2,%3}, [%4];"
                 : "=r"(r[0]), "=r"(r[1]), "=r"(r[2]), "=r"(r[3]) : "r"(addr));
}
__device__ __forceinline__ void mma_f16(float* c, const uint32_t* a, uint32_t b0, uint32_t b1) {
    asm volatile("mma.sync.aligned.m16n8k16.row.col.f32.f16.f16.f32 "
                 "{%0,%1,%2,%3}, {%4,%5,%6,%7}, {%8,%9}, {%0,%1,%2,%3};"
                 : "+f"(c[0]), "+f"(c[1]), "+f"(c[2]), "+f"(c[3])
                 : "r"(a[0]), "r"(a[1]), "r"(a[2]), "r"(a[3]), "r"(b0), "r"(b1));
}
__device__ __forceinline__ void bulk_g2s(uint32_t sdst, const void* gsrc,
                                         uint32_t bytes, uint32_t mbar) {
    asm volatile(
        "cp.async.bulk.shared::cluster.global.mbarrier::complete_tx::bytes [%0], [%1], %2, [%3];"
        :: "r"(sdst), "l"(gsrc), "r"(bytes), "r"(mbar) : "memory");
}
__device__ __forceinline__ void mbar_init(uint32_t mbar, uint32_t cnt) {
    asm volatile("mbarrier.init.shared.b64 [%0], %1;" :: "r"(mbar), "r"(cnt) : "memory");
}
__device__ __forceinline__ void mbar_expect_tx(uint32_t mbar, uint32_t bytes) {
    asm volatile("mbarrier.arrive.expect_tx.shared.b64 _, [%0], %1;"
                 :: "r"(mbar), "r"(bytes) : "memory");
}
__device__ __forceinline__ void mbar_arrive(uint32_t mbar) {
    asm volatile("mbarrier.arrive.release.cta.shared::cta.b64 _, [%0];"
                 :: "r"(mbar) : "memory");
}
__device__ __forceinline__ void mbar_wait(uint32_t mbar, uint32_t parity) {
    uint32_t done;
    asm volatile(
        "{\n\t.reg .pred p;\n\t"
        "mbarrier.try_wait.parity.acquire.cta.shared::cta.b64 p, [%1], %2;\n\t"
        "selp.b32 %0, 1, 0, p;\n\t}"
        : "=r"(done) : "r"(mbar), "r"(parity) : "memory");
    if (!done) {
        asm volatile(
            "{\n\t.reg .pred P1;\n\t"
            "W_%=:\n\t"
            "mbarrier.try_wait.parity.acquire.cta.shared::cta.b64 P1, [%0], %1, 0x989680;\n\t"
            "@P1 bra.uni D_%=;\n\t"
            "bra.uni W_%=;\n\t"
            "D_%=:\n\t}"
            :: "r"(mbar), "r"(parity) : "memory");
    }
}
__device__ __forceinline__ void pdl_trigger() {
#if defined(__CUDA_ARCH__) && __CUDA_ARCH__ >= 900
    cudaTriggerProgrammaticLaunchCompletion();
#endif
}
__device__ __forceinline__ void pdl_sync() {
#if defined(__CUDA_ARCH__) && __CUDA_ARCH__ >= 900
    cudaGridDependencySynchronize();
#endif
}

// ---------------- SMEM layout ----------------
static constexpr int SA      = 0;
static constexpr int SB      = 16384;
static constexpr int STAGE   = 32768;
static constexpr int NSTAGE  = 3;
static constexpr int SXE     = NSTAGE * STAGE;            // 98304, A ext 4KB
static constexpr int SWE     = SXE + 4096;                // B ext 4KB
static constexpr int SM_FULL = SWE + 4096;                // 106496
static constexpr int SM_CONS = SM_FULL + NSTAGE * 8;
static constexpr int SM_EXTF = SM_CONS + NSTAGE * 8;
static constexpr int SMEM_BYTES = SM_EXTF + 8;

// state element index (fp16 units) for (m, n), write-phase wph
__device__ __forceinline__ size_t st_idx(int m, int n, int wph) {
    int l = m & (LSEQ - 1);
    size_t row = (size_t)(m >> 11) * CHROW + l + 1;
    int ph  = ((l + wph) & 7) << 4;
    int raw = (n & 63) * 2;
    return (size_t)(n >> 6) * A_CH_ELEMS + row * 64 + ((raw ^ ph) >> 1);
}

// complementary fp16 rounding pair
__device__ __forceinline__ void round_pair(float w, __half& ha, __half& hb) {
    ha = __float2half(w);
    hb = __float2half(w + (w - __half2float(ha)));   // opposite-side neighbor
}

// ---------------------------------------------------------------------------
// prep: state#1 = relu(x@W1^T + b1 + b2) in fp32 -> fp16 swizzled state.
// Each thread computes TWO adjacent n (even n) -> half2 stores.
// ---------------------------------------------------------------------------
__global__ void prep_kernel(const float* __restrict__ x,
                            const float* __restrict__ W1,
                            const float* __restrict__ b1,
                            const float* __restrict__ b2) {
    int idx = blockIdx.x * blockDim.x + threadIdx.x;
    if (idx >= MTOT * (DDIM / 2)) return;
    int n = (idx & 127) * 2;
    int m = idx >> 7;
    int b = m / LSEQ;
    int l = m & (LSEQ - 1);
    const float* xp = x + (size_t)b * 4 * LSEQ + l;
    float xv[4];
#pragma unroll
    for (int dd = 0; dd < 4; dd++) xv[dd] = xp[dd * LSEQ];
    float s0 = b1[n]     + b2[n];
    float s1 = b1[n + 1] + b2[n + 1];
#pragma unroll
    for (int dd = 0; dd < 4; dd++) {
        s0 = fmaf(xv[dd], W1[n * 4 + dd],       s0);
        s1 = fmaf(xv[dd], W1[(n + 1) * 4 + dd], s1);
    }
    __half2 hv;
    hv.x = __float2half(fmaxf(s0, 0.0f));
    hv.y = __float2half(fmaxf(s1, 0.0f));
    *reinterpret_cast<__half2*>(&g_up[0][st_idx(m, n, +1)]) = hv;
    *reinterpret_cast<__half2*>(&g_dn[0][st_idx(m, n, -1)]) = hv;
}

// build x_ext rows: [xh(4), xh(4), xl(4), 1, 1, 0, 0] per m
__global__ void xext_kernel(const float* __restrict__ x) {
    int m = blockIdx.x * blockDim.x + threadIdx.x;
    if (m >= MTOT) return;
    int b = m >> 11, l = m & (LSEQ - 1);
    __half r[16];
#pragma unroll
    for (int j = 0; j < 16; j++) r[j] = __float2half(0.0f);
#pragma unroll
    for (int dd = 0; dd < 4; dd++) {
        float xv = x[(size_t)b * 4 * LSEQ + dd * LSEQ + l];
        __half xh = __float2half(xv);
        r[dd]     = xh;
        r[4 + dd] = xh;
        r[8 + dd] = __float2half(xv - __half2float(xh));
    }
    r[12] = __float2half(1.0f);
    r[13] = __float2half(1.0f);
    uint4* dst = reinterpret_cast<uint4*>(g_xe + (size_t)m * 16);
    dst[0] = reinterpret_cast<const uint4*>(r)[0];
    dst[1] = reinterpret_cast<const uint4*>(r)[1];
}

// split W2/W4 into dithered fp16 chunk-major swizzled layout + exact ext rows
__global__ void split_w_kernel(const float* __restrict__ W2,
                               const float* __restrict__ W4,
                               const float* __restrict__ W1,
                               const float* __restrict__ b1,
                               const float* __restrict__ b2,
                               const float* __restrict__ W3,
                               const float* __restrict__ b3,
                               const float* __restrict__ b4) {
    int idx = blockIdx.x * blockDim.x + threadIdx.x;   // (n, k)
    if (idx >= DDIM * DDIM) return;
    int n = idx >> 8, k = idx & 255;
    int ph = (n & 7) << 4;
    size_t off = (size_t)(k >> 6) * W_CH + (size_t)n * 64 + ((((k & 63) * 2)) ^ ph) / 2;
    __half ha, hb;
    round_pair(W2[idx], ha, hb);
    g_W2[0][off] = ha;
    g_W2[1][off] = hb;
    round_pair(W4[idx], ha, hb);
    g_W4[0][off] = ha;
    g_W4[1][off] = hb;
    if (k == 0) {
        __half r2[16], r4[16];
#pragma unroll
        for (int j = 0; j < 16; j++) { r2[j] = __float2half(0.0f); r4[j] = r2[j]; }
#pragma unroll
        for (int dd = 0; dd < 4; dd++) {
            float w1v = W1[n * 4 + dd];
            __half w1h = __float2half(w1v);
            r2[dd]     = w1h;
            r2[4 + dd] = __float2half(w1v - __half2float(w1h));
            r2[8 + dd] = w1h;
            float w3v = W3[n * 4 + dd];
            __half w3h = __float2half(w3v);
            r4[dd]     = w3h;
            r4[4 + dd] = __float2half(w3v - __half2float(w3h));
            r4[8 + dd] = w3h;
        }
        float bias2 = b1[n] + b2[n];
        __half b2h = __float2half(bias2);
        r2[12] = b2h;
        r2[13] = __float2half(bias2 - __half2float(b2h));
        float bias4 = b3[n] + 2.0f * b4[n];
        __half b4h = __float2half(bias4);
        r4[12] = b4h;
        r4[13] = __float2half(bias4 - __half2float(b4h));
        uint4* d2 = reinterpret_cast<uint4*>(g_w2e + (size_t)n * 16);
        uint4* d4 = reinterpret_cast<uint4*>(g_w4e + (size_t)n * 16);
        d2[0] = reinterpret_cast<const uint4*>(r2)[0];
        d2[1] = reinterpret_cast<const uint4*>(r2)[1];
        d4[0] = reinterpret_cast<const uint4*>(r4)[0];
        d4[1] = reinterpret_cast<const uint4*>(r4)[1];
    }
}

// split A/B prefetch: each expect_tx is one arrival; stage barriers count=2.
__device__ __forceinline__ void issue_B(uint32_t sbase, uint32_t mbar,
                                        const __half* w, int n0, int c) {
    mbar_expect_tx(mbar, 16384);
    bulk_g2s(sbase + SB, w + (size_t)c * W_CH + (size_t)n0 * 64, 16384, mbar);
}
__device__ __forceinline__ void issue_A(uint32_t sbase, uint32_t mbar,
                                        const __half* in, size_t arow, int c) {
    mbar_expect_tx(mbar, 16384);
    bulk_g2s(sbase + SA, in + (size_t)c * A_CH_ELEMS + arow * 64, 16384, mbar);
}
// ext pair: x rows + weight-ext rows (4KB each), one expect (count=1)
__device__ __forceinline__ void issue_ext(uint32_t sb, uint32_t mbar,
                                          const __half* we, int m0, int n0) {
    mbar_expect_tx(mbar, 8192);
    bulk_g2s(sb + SXE, g_xe + (size_t)m0 * 16, 4096, mbar);
    bulk_g2s(sb + SWE, we + (size_t)n0 * 16, 4096, mbar);
}

// compute one k64 stage, single-pass fp16. warp tile 32x64.
__device__ __forceinline__ void compute_stage(uint32_t base, int lane, int wm, int wn,
                                              float acc[2][8][4]) {
    const uint32_t swz  = (uint32_t)(lane & 7) << 4;
    const uint32_t rlo  = (uint32_t)(lane & 15);
    const uint32_t hi16 = (uint32_t)(lane >> 4) * 16;
#pragma unroll
    for (int ks = 0; ks < 4; ks++) {
        uint32_t ch = ((uint32_t)(ks * 32) + hi16) ^ swz;
        uint32_t ah[2][4];
#pragma unroll
        for (int mt = 0; mt < 2; mt++)
            ldm_x4(ah[mt], base + SA + (wm * 32 + mt * 16 + rlo) * 128 + ch);
        uint32_t bf[4][4];
#pragma unroll
        for (int pr = 0; pr < 4; pr++)
            ldm_x4(bf[pr], base + SB + ((wn * 4 + pr) * 16 + rlo) * 128 + ch);
#pragma unroll
        for (int pr = 0; pr < 4; pr++)
#pragma unroll
            for (int mt = 0; mt < 2; mt++) {
                mma_f16(acc[mt][pr * 2],     ah[mt], bf[pr][0], bf[pr][2]);
                mma_f16(acc[mt][pr * 2 + 1], ah[mt], bf[pr][1], bf[pr][3]);
            }
    }
}

// ext k16 step: rows of 32B, unswizzled
__device__ __forceinline__ void compute_ext(uint32_t sb, int lane, int wm, int wn,
                                            float acc[2][8][4]) {
    const uint32_t rlo  = (uint32_t)(lane & 15);
    const uint32_t hi16 = (uint32_t)(lane >> 4) * 16;
    uint32_t ah[2][4];
#pragma unroll
    for (int mt = 0; mt < 2; mt++)
        ldm_x4(ah[mt], sb + SXE + (wm * 32 + mt * 16 + rlo) * 32 + hi16);
    uint32_t bf[4][4];
#pragma unroll
    for (int pr = 0; pr < 4; pr++)
        ldm_x4(bf[pr], sb + SWE + ((wn * 4 + pr) * 16 + rlo) * 32 + hi16);
#pragma unroll
    for (int pr = 0; pr < 4; pr++)
#pragma unroll
        for (int mt = 0; mt < 2; mt++) {
            mma_f16(acc[mt][pr * 2],     ah[mt], bf[pr][0], bf[pr][2]);
            mma_f16(acc[mt][pr * 2 + 1], ah[mt], bf[pr][1], bf[pr][3]);
        }
}

// ---------------------------------------------------------------------------
// DP iteration: out = relu(shift(in)@W2^T + x@W1^T + b1 + b2), dithered W2.
// PDL: ext + B stages issued pre-sync; A stages post-sync.
// ---------------------------------------------------------------------------
__global__ __launch_bounds__(NTHR, 2) void dp_iter_kernel(int src, int wvar, int pdl) {
    extern __shared__ char smem[];
    const uint32_t sb = smem_u32(smem);
    const int tid = threadIdx.x, lane = tid & 31, wid = tid >> 5;
    const int wm = wid >> 1, wn = wid & 1;
    const int m0 = blockIdx.x * BM;
    const int n0 = blockIdx.y * BN;
    const int ln = blockIdx.z;

    const __half* in  = ln ? g_dn[src]     : g_up[src];
    __half*       out = ln ? g_dn[src ^ 1] : g_up[src ^ 1];
    const __half* w2  = g_W2[wvar];
    const int shift = ln ? 1 : -1;
    const int wph = -shift;
    const size_t arow = (size_t)(m0 >> 11) * CHROW + (m0 & (LSEQ - 1)) + 1 + shift;

    if (tid == 0) {
        for (int s = 0; s < NSTAGE; s++) {
            mbar_init(sb + SM_FULL + s * 8, 2);   // A arrive + B arrive
            mbar_init(sb + SM_CONS + s * 8, 8);
        }
        mbar_init(sb + SM_EXTF, 1);
    }
    __syncthreads();
    // weight-side prefetch (independent of predecessor's state writes)
    if (tid == 0) {
        issue_ext(sb, sb + SM_EXTF, g_w2e, m0, n0);
        for (int s = 0; s < NSTAGE; s++)
            issue_B(sb + s * STAGE, sb + SM_FULL + s * 8, w2, n0, s);
    }
    pdl_trigger();
    if (pdl) pdl_sync();
    // state-side prefetch
    if (tid == 0)
        for (int s = 0; s < NSTAGE; s++)
            issue_A(sb + s * STAGE, sb + SM_FULL + s * 8, in, arow, s);

    float acc[2][8][4];
#pragma unroll
    for (int i = 0; i < 2; i++)
#pragma unroll
        for (int j = 0; j < 8; j++)
#pragma unroll
            for (int q = 0; q < 4; q++) acc[i][j][q] = 0.0f;

    const bool prod = (wid == 0) && elect_one();
    int buf = 0, par = 0;
#pragma unroll 1
    for (int c = 0; c < 4; c++) {
        mbar_wait(sb + SM_FULL + buf * 8, par);
        compute_stage(sb + buf * STAGE, lane, wm, wn, acc);
        if (c == 0) {      // only buffer 0 is ever refilled (chunk 3)
            if (elect_one()) mbar_arrive(sb + SM_CONS + buf * 8);
            if (prod) {
                mbar_wait(sb + SM_CONS + buf * 8, par);
                issue_B(sb + buf * STAGE, sb + SM_FULL + buf * 8, w2, n0, 3);
                issue_A(sb + buf * STAGE, sb + SM_FULL + buf * 8, in, arow, 3);
            }
        }
        if (++buf == NSTAGE) { buf = 0; par ^= 1; }
    }
    mbar_wait(sb + SM_EXTF, 0);
    compute_ext(sb, lane, wm, wn, acc);

    // epilogue: relu(acc) -> fp16 state, swizzled layout (no global reads)
#pragma unroll
    for (int mt = 0; mt < 2; mt++) {
#pragma unroll
        for (int h = 0; h < 2; h++) {
            int m = m0 + wm * 32 + mt * 16 + (lane >> 2) + h * 8;
            int l = m & (LSEQ - 1);
            size_t rowbase = ((size_t)(m >> 11) * CHROW + l + 1) * 64;
            int ph = ((l + wph) & 7) << 4;
#pragma unroll
            for (int nt = 0; nt < 8; nt++) {
                int n = n0 + wn * 64 + nt * 8 + (lane & 3) * 2;
                __half2 hv;
                hv.x = __float2half(fmaxf(acc[mt][nt][2 * h],     0.0f));
                hv.y = __float2half(fmaxf(acc[mt][nt][2 * h + 1], 0.0f));
                size_t off = (size_t)(n >> 6) * A_CH_ELEMS + rowbase
                           + ((((n & 63) * 2) ^ ph) >> 1);
                *reinterpret_cast<__half2*>(out + off) = hv;
            }
        }
    }
}

// ---------------------------------------------------------------------------
// final: miu = relu(x@W3^T + b3 + 2*b4 + W4a*up[j-1] + W4b*down[j+1])
// 8 stages (up variant 0, down variant 1) + ext. grid (m_tiles, 2). PDL.
// ---------------------------------------------------------------------------
__global__ __launch_bounds__(NTHR, 2) void final_kernel(float* __restrict__ out,
                                                        int src) {
    extern __shared__ char smem[];
    const uint32_t sb = smem_u32(smem);
    const int tid = threadIdx.x, lane = tid & 31, wid = tid >> 5;
    const int wm = wid >> 1, wn = wid & 1;
    const int m0 = blockIdx.x * BM;
    const int n0 = blockIdx.y * BN;
    const size_t rbase = (size_t)(m0 >> 11) * CHROW + (m0 & (LSEQ - 1)) + 1;
    const size_t arow_up = rbase - 1;
    const size_t arow_dn = rbase + 1;
    const __half* upp = g_up[src];
    const __half* dnp = g_dn[src];

    if (tid == 0) {
        for (int s = 0; s < NSTAGE; s++) {
            mbar_init(sb + SM_FULL + s * 8, 2);
            mbar_init(sb + SM_CONS + s * 8, 8);
        }
        mbar_init(sb + SM_EXTF, 1);
    }
    __syncthreads();
    if (tid == 0) {
        issue_ext(sb, sb + SM_EXTF, g_w4e, m0, n0);
        for (int s = 0; s < NSTAGE; s++)
            issue_B(sb + s * STAGE, sb + SM_FULL + s * 8, g_W4[0], n0, s);
    }
    pdl_trigger();
    pdl_sync();
    if (tid == 0)
        for (int s = 0; s < NSTAGE; s++)
            issue_A(sb + s * STAGE, sb + SM_FULL + s * 8, upp, arow_up, s);

    float acc[2][8][4];
#pragma unroll
    for (int i = 0; i < 2; i++)
#pragma unroll
        for (int j = 0; j < 8; j++)
#pragma unroll
            for (int q = 0; q < 4; q++) acc[i][j][q] = 0.0f;

    const bool prod = (wid == 0) && elect_one();
    int buf = 0, par = 0;
#pragma unroll 1
    for (int t = 0; t < 8; t++) {
        mbar_wait(sb + SM_FULL + buf * 8, par);
        compute_stage(sb + buf * STAGE, lane, wm, wn, acc);
        if (t < 5) {
            if (elect_one()) mbar_arrive(sb + SM_CONS + buf * 8);
            if (prod) {
                mbar_wait(sb + SM_CONS + buf * 8, par);
                int tn = t + 3;
                int phx = tn >> 2;
                const __half* arr = phx ? dnp : upp;
                size_t sr = phx ? arow_dn : arow_up;
                issue_B(sb + buf * STAGE, sb + SM_FULL + buf * 8, g_W4[phx], n0, tn & 3);
                issue_A(sb + buf * STAGE, sb + SM_FULL + buf * 8, arr, sr, tn & 3);
            }
        }
        if (++buf == NSTAGE) { buf = 0; par ^= 1; }
    }
    mbar_wait(sb + SM_EXTF, 0);
    compute_ext(sb, lane, wm, wn, acc);

    // epilogue: relu(acc) -> fp32 out (linear layout)
#pragma unroll
    for (int mt = 0; mt < 2; mt++) {
#pragma unroll
        for (int h = 0; h < 2; h++) {
            int m = m0 + wm * 32 + mt * 16 + (lane >> 2) + h * 8;
            float* orow = out + (size_t)m * DDIM;
#pragma unroll
            for (int nt = 0; nt < 8; nt++) {
                int n = n0 + wn * 64 + nt * 8 + (lane & 3) * 2;
                float2 o = make_float2(fmaxf(acc[mt][nt][2 * h],     0.0f),
                                       fmaxf(acc[mt][nt][2 * h + 1], 0.0f));
                *reinterpret_cast<float2*>(orow + n) = o;
            }
        }
    }
}

// ---------------------------------------------------------------------------
extern "C" void kernel_launch(void* const* d_in, const int* in_sizes, int n_in,
                              void* d_out, int out_size) {
    const float* x  = (const float*)d_in[0];
    const float* W1 = (const float*)d_in[1];
    const float* b1 = (const float*)d_in[2];
    const float* W2 = (const float*)d_in[3];
    const float* b2 = (const float*)d_in[4];
    const float* W3 = (const float*)d_in[5];
    const float* b3 = (const float*)d_in[6];
    const float* W4 = (const float*)d_in[7];
    const float* b4 = (const float*)d_in[8];
    float* out = (float*)d_out;

    cudaFuncSetAttribute(dp_iter_kernel, cudaFuncAttributeMaxDynamicSharedMemorySize, SMEM_BYTES);
    cudaFuncSetAttribute(final_kernel,   cudaFuncAttributeMaxDynamicSharedMemorySize, SMEM_BYTES);

    prep_kernel<<<(MTOT * (DDIM / 2) + 255) / 256, 256>>>(x, W1, b1, b2);
    xext_kernel<<<(MTOT + 255) / 256, 256>>>(x);
    split_w_kernel<<<(DDIM * DDIM + 255) / 256, 256>>>(W2, W4, W1, b1, b2, W3, b3, b4);

    // iteration 1: plain launch (its B prefetch must not race split_w_kernel)
    int src = 0;
    dp_iter_kernel<<<dim3(MTOT / BM, 2, 2), NTHR, SMEM_BYTES>>>(src, 0, 0);
    src ^= 1;

    // iterations 2..7 + final: PDL launches (weight prologue overlaps tail)
    cudaLaunchAttribute attrs[1];
    attrs[0].id = cudaLaunchAttributeProgrammaticStreamSerialization;
    attrs[0].val.programmaticStreamSerializationAllowed = 1;

    for (int t = 1; t < 7; t++) {
        cudaLaunchConfig_t cfg = {};
        cfg.gridDim = dim3(MTOT / BM, 2, 2);
        cfg.blockDim = dim3(NTHR, 1, 1);
        cfg.dynamicSmemBytes = SMEM_BYTES;
        cfg.stream = 0;
        cfg.attrs = attrs;
        cfg.numAttrs = 1;
        cudaLaunchKernelEx(&cfg, dp_iter_kernel, src, t & 1, 1);
        src ^= 1;
    }
    {
        cudaLaunchConfig_t cfg = {};
        cfg.gridDim = dim3(MTOT / BM, 2);
        cfg.blockDim = dim3(NTHR, 1, 1);
        cfg.dynamicSmemBytes = SMEM_BYTES;
        cfg.stream = 0;
        cfg.attrs = attrs;
        cfg.numAttrs = 1;
        cudaLaunchKernelEx(&cfg, final_kernel, out, src);
    }
}

// round 16
// speedup vs baseline: 1.5925x; 1.0299x over previous
#include <cuda_runtime.h>
#include <cuda_fp16.h>
#include <cstdint>

#define BSZ   16
#define LSEQ  2048
#define DDIM  256
#define MTOT  (BSZ * LSEQ)    // 32768
#define BM    128
#define BN    128
#define NTHR  256

// A (state): single fp16, 4 chunks of k64; row = 64 fp16 = 128B, SW128 phase
// baked per (l + wph). B (weights): single fp16, 4 chunks of k64, phase (n&7),
// TWO complementary-rounded variants alternated across iterations (dither).
// ext: k16 tail computing a = x@W1^T + bias exactly via hi/lo cross terms.
// Iter-1 dn lane reads g_up[0] (wph=+1 baking) with A-swizzle lane offset +2.
#define CHROW  2056
#define A_CH_ELEMS ((size_t)BSZ * CHROW * 64)   // per k64 chunk
#define W_CH   (256 * 64)

// ---------------- global state (static .bss; pad rows stay zero) ----------
__device__ __align__(128) __half g_up[2][4 * A_CH_ELEMS];
__device__ __align__(128) __half g_dn[2][4 * A_CH_ELEMS];
__device__ __align__(128) __half g_W2[2][4 * W_CH];   // [variant][chunk...]
__device__ __align__(128) __half g_W4[2][4 * W_CH];
__device__ __align__(128) __half g_xe[(size_t)MTOT * 16];
__device__ __align__(128) __half g_w2e[256 * 16];
__device__ __align__(128) __half g_w4e[256 * 16];

// ---------------- helpers ----------------
__device__ __forceinline__ uint32_t smem_u32(const void* p) {
    uint32_t a;
    asm("{ .reg .u64 t; cvta.to.shared.u64 t, %1; cvt.u32.u64 %0, t; }" : "=r"(a) : "l"(p));
    return a;
}
__device__ __forceinline__ uint32_t elect_one() {
    uint32_t pred;
    asm volatile("{\n\t.reg .pred p;\n\telect.sync _|p, 0xFFFFFFFF;\n\t"
                 "selp.b32 %0, 1, 0, p;\n\t}" : "=r"(pred));
    return pred;
}
__device__ __forceinline__ void ldm_x4(uint32_t* r, uint32_t addr) {
    asm volatile("ldmatrix.sync.aligned.m8n8.x4.shared.b16 {%0,%1,%2,%3}, [%4];"
                 : "=r"(r[0]), "=r"(r[1]), "=r"(r[2]), "=r"(r[3]) : "r"(addr));
}
__device__ __forceinline__ void mma_f16(float* c, const uint32_t* a, uint32_t b0, uint32_t b1) {
    asm volatile("mma.sync.aligned.m16n8k16.row.col.f32.f16.f16.f32 "
                 "{%0,%1,%2,%3}, {%4,%5,%6,%7}, {%8,%9}, {%0,%1,%2,%3};"
                 : "+f"(c[0]), "+f"(c[1]), "+f"(c[2]), "+f"(c[3])
                 : "r"(a[0]), "r"(a[1]), "r"(a[2]), "r"(a[3]), "r"(b0), "r"(b1));
}
__device__ __forceinline__ void bulk_g2s(uint32_t sdst, const void* gsrc,
                                         uint32_t bytes, uint32_t mbar) {
    asm volatile(
        "cp.async.bulk.shared::cluster.global.mbarrier::complete_tx::bytes [%0], [%1], %2, [%3];"
        :: "r"(sdst), "l"(gsrc), "r"(bytes), "r"(mbar) : "memory");
}
__device__ __forceinline__ void mbar_init(uint32_t mbar, uint32_t cnt) {
    asm volatile("mbarrier.init.shared.b64 [%0], %1;" :: "r"(mbar), "r"(cnt) : "memory");
}
__device__ __forceinline__ void mbar_expect_tx(uint32_t mbar, uint32_t bytes) {
    asm volatile("mbarrier.arrive.expect_tx.shared.b64 _, [%0], %1;"
                 :: "r"(mbar), "r"(bytes) : "memory");
}
__device__ __forceinline__ void mbar_arrive(uint32_t mbar) {
    asm volatile("mbarrier.arrive.release.cta.shared::cta.b64 _, [%0];"
                 :: "r"(mbar) : "memory");
}
__device__ __forceinline__ void mbar_wait(uint32_t mbar, uint32_t parity) {
    uint32_t done;
    asm volatile(
        "{\n\t.reg .pred p;\n\t"
        "mbarrier.try_wait.parity.acquire.cta.shared::cta.b64 p, [%1], %2;\n\t"
        "selp.b32 %0, 1, 0, p;\n\t}"
        : "=r"(done) : "r"(mbar), "r"(parity) : "memory");
    if (!done) {
        asm volatile(
            "{\n\t.reg .pred P1;\n\t"
            "W_%=:\n\t"
            "mbarrier.try_wait.parity.acquire.cta.shared::cta.b64 P1, [%0], %1, 0x989680;\n\t"
            "@P1 bra.uni D_%=;\n\t"
            "bra.uni W_%=;\n\t"
            "D_%=:\n\t}"
            :: "r"(mbar), "r"(parity) : "memory");
    }
}
__device__ __forceinline__ void pdl_trigger() {
#if defined(__CUDA_ARCH__) && __CUDA_ARCH__ >= 900
    cudaTriggerProgrammaticLaunchCompletion();
#endif
}
__device__ __forceinline__ void pdl_sync() {
#if defined(__CUDA_ARCH__) && __CUDA_ARCH__ >= 900
    cudaGridDependencySynchronize();
#endif
}

// ---------------- SMEM layout ----------------
static constexpr int SA      = 0;
static constexpr int SB      = 16384;
static constexpr int STAGE   = 32768;
static constexpr int NSTAGE  = 3;
static constexpr int SXE     = NSTAGE * STAGE;            // 98304, A ext 4KB
static constexpr int SWE     = SXE + 4096;                // B ext 4KB
static constexpr int SM_FULL = SWE + 4096;                // 106496
static constexpr int SM_CONS = SM_FULL + NSTAGE * 8;
static constexpr int SM_EXTF = SM_CONS + NSTAGE * 8;
static constexpr int SMEM_BYTES = SM_EXTF + 8;

// state element index (fp16 units) for (m, n), write-phase wph
__device__ __forceinline__ size_t st_idx(int m, int n, int wph) {
    int l = m & (LSEQ - 1);
    size_t row = (size_t)(m >> 11) * CHROW + l + 1;
    int ph  = ((l + wph) & 7) << 4;
    int raw = (n & 63) * 2;
    return (size_t)(n >> 6) * A_CH_ELEMS + row * 64 + ((raw ^ ph) >> 1);
}

// complementary fp16 rounding pair
__device__ __forceinline__ void round_pair(float w, __half& ha, __half& hb) {
    ha = __float2half(w);
    hb = __float2half(w + (w - __half2float(ha)));   // opposite-side neighbor
}

// ---------------------------------------------------------------------------
// prep: state#1 = relu(x@W1^T + b1 + b2) -> g_up[0] ONLY (wph=+1 baking).
// Iter-1 dn lane reads this array with A-swizzle offset +2.
// ---------------------------------------------------------------------------
__global__ void prep_kernel(const float* __restrict__ x,
                            const float* __restrict__ W1,
                            const float* __restrict__ b1,
                            const float* __restrict__ b2) {
    pdl_trigger();
    int idx = blockIdx.x * blockDim.x + threadIdx.x;
    if (idx >= MTOT * (DDIM / 2)) return;
    int n = (idx & 127) * 2;
    int m = idx >> 7;
    int b = m / LSEQ;
    int l = m & (LSEQ - 1);
    const float* xp = x + (size_t)b * 4 * LSEQ + l;
    float xv[4];
#pragma unroll
    for (int dd = 0; dd < 4; dd++) xv[dd] = xp[dd * LSEQ];
    float s0 = b1[n]     + b2[n];
    float s1 = b1[n + 1] + b2[n + 1];
#pragma unroll
    for (int dd = 0; dd < 4; dd++) {
        s0 = fmaf(xv[dd], W1[n * 4 + dd],       s0);
        s1 = fmaf(xv[dd], W1[(n + 1) * 4 + dd], s1);
    }
    __half2 hv;
    hv.x = __float2half(fmaxf(s0, 0.0f));
    hv.y = __float2half(fmaxf(s1, 0.0f));
    *reinterpret_cast<__half2*>(&g_up[0][st_idx(m, n, +1)]) = hv;
}

// build x_ext rows: [xh(4), xh(4), xl(4), 1, 1, 0, 0] per m
__global__ void xext_kernel(const float* __restrict__ x) {
    int m = blockIdx.x * blockDim.x + threadIdx.x;
    if (m >= MTOT) return;
    int b = m >> 11, l = m & (LSEQ - 1);
    __half r[16];
#pragma unroll
    for (int j = 0; j < 16; j++) r[j] = __float2half(0.0f);
#pragma unroll
    for (int dd = 0; dd < 4; dd++) {
        float xv = x[(size_t)b * 4 * LSEQ + dd * LSEQ + l];
        __half xh = __float2half(xv);
        r[dd]     = xh;
        r[4 + dd] = xh;
        r[8 + dd] = __float2half(xv - __half2float(xh));
    }
    r[12] = __float2half(1.0f);
    r[13] = __float2half(1.0f);
    uint4* dst = reinterpret_cast<uint4*>(g_xe + (size_t)m * 16);
    dst[0] = reinterpret_cast<const uint4*>(r)[0];
    dst[1] = reinterpret_cast<const uint4*>(r)[1];
}

// split W2/W4 into dithered fp16 chunk-major swizzled layout + exact ext rows
__global__ void split_w_kernel(const float* __restrict__ W2,
                               const float* __restrict__ W4,
                               const float* __restrict__ W1,
                               const float* __restrict__ b1,
                               const float* __restrict__ b2,
                               const float* __restrict__ W3,
                               const float* __restrict__ b3,
                               const float* __restrict__ b4) {
    int idx = blockIdx.x * blockDim.x + threadIdx.x;   // (n, k)
    if (idx >= DDIM * DDIM) return;
    int n = idx >> 8, k = idx & 255;
    int ph = (n & 7) << 4;
    size_t off = (size_t)(k >> 6) * W_CH + (size_t)n * 64 + ((((k & 63) * 2)) ^ ph) / 2;
    __half ha, hb;
    round_pair(W2[idx], ha, hb);
    g_W2[0][off] = ha;
    g_W2[1][off] = hb;
    round_pair(W4[idx], ha, hb);
    g_W4[0][off] = ha;
    g_W4[1][off] = hb;
    if (k == 0) {
        __half r2[16], r4[16];
#pragma unroll
        for (int j = 0; j < 16; j++) { r2[j] = __float2half(0.0f); r4[j] = r2[j]; }
#pragma unroll
        for (int dd = 0; dd < 4; dd++) {
            float w1v = W1[n * 4 + dd];
            __half w1h = __float2half(w1v);
            r2[dd]     = w1h;
            r2[4 + dd] = __float2half(w1v - __half2float(w1h));
            r2[8 + dd] = w1h;
            float w3v = W3[n * 4 + dd];
            __half w3h = __float2half(w3v);
            r4[dd]     = w3h;
            r4[4 + dd] = __float2half(w3v - __half2float(w3h));
            r4[8 + dd] = w3h;
        }
        float bias2 = b1[n] + b2[n];
        __half b2h = __float2half(bias2);
        r2[12] = b2h;
        r2[13] = __float2half(bias2 - __half2float(b2h));
        float bias4 = b3[n] + 2.0f * b4[n];
        __half b4h = __float2half(bias4);
        r4[12] = b4h;
        r4[13] = __float2half(bias4 - __half2float(b4h));
        uint4* d2 = reinterpret_cast<uint4*>(g_w2e + (size_t)n * 16);
        uint4* d4 = reinterpret_cast<uint4*>(g_w4e + (size_t)n * 16);
        d2[0] = reinterpret_cast<const uint4*>(r2)[0];
        d2[1] = reinterpret_cast<const uint4*>(r2)[1];
        d4[0] = reinterpret_cast<const uint4*>(r4)[0];
        d4[1] = reinterpret_cast<const uint4*>(r4)[1];
    }
}

// split A/B prefetch: each expect_tx is one arrival; stage barriers count=2.
__device__ __forceinline__ void issue_B(uint32_t sbase, uint32_t mbar,
                                        const __half* w, int n0, int c) {
    mbar_expect_tx(mbar, 16384);
    bulk_g2s(sbase + SB, w + (size_t)c * W_CH + (size_t)n0 * 64, 16384, mbar);
}
__device__ __forceinline__ void issue_A(uint32_t sbase, uint32_t mbar,
                                        const __half* in, size_t arow, int c) {
    mbar_expect_tx(mbar, 16384);
    bulk_g2s(sbase + SA, in + (size_t)c * A_CH_ELEMS + arow * 64, 16384, mbar);
}
// ext pair: x rows + weight-ext rows (4KB each), one expect (count=1)
__device__ __forceinline__ void issue_ext(uint32_t sb, uint32_t mbar,
                                          const __half* we, int m0, int n0) {
    mbar_expect_tx(mbar, 8192);
    bulk_g2s(sb + SXE, g_xe + (size_t)m0 * 16, 4096, mbar);
    bulk_g2s(sb + SWE, we + (size_t)n0 * 16, 4096, mbar);
}

// compute one k64 stage, single-pass fp16. warp tile 32x64.
// aoff = A-tile swizzle lane offset (0 normally; 2 for iter-1 dn lane).
__device__ __forceinline__ void compute_stage(uint32_t base, int lane, int wm, int wn,
                                              int aoff, float acc[2][8][4]) {
    const uint32_t swzA = (uint32_t)((lane + aoff) & 7) << 4;
    const uint32_t swzB = (uint32_t)(lane & 7) << 4;
    const uint32_t rlo  = (uint32_t)(lane & 15);
    const uint32_t hi16 = (uint32_t)(lane >> 4) * 16;
#pragma unroll
    for (int ks = 0; ks < 4; ks++) {
        uint32_t cbase = (uint32_t)(ks * 32) + hi16;
        uint32_t chA = cbase ^ swzA;
        uint32_t chB = cbase ^ swzB;
        uint32_t ah[2][4];
#pragma unroll
        for (int mt = 0; mt < 2; mt++)
            ldm_x4(ah[mt], base + SA + (wm * 32 + mt * 16 + rlo) * 128 + chA);
        uint32_t bf[4][4];
#pragma unroll
        for (int pr = 0; pr < 4; pr++)
            ldm_x4(bf[pr], base + SB + ((wn * 4 + pr) * 16 + rlo) * 128 + chB);
#pragma unroll
        for (int pr = 0; pr < 4; pr++)
#pragma unroll
            for (int mt = 0; mt < 2; mt++) {
                mma_f16(acc[mt][pr * 2],     ah[mt], bf[pr][0], bf[pr][2]);
                mma_f16(acc[mt][pr * 2 + 1], ah[mt], bf[pr][1], bf[pr][3]);
            }
    }
}

// ext k16 step: rows of 32B, unswizzled
__device__ __forceinline__ void compute_ext(uint32_t sb, int lane, int wm, int wn,
                                            float acc[2][8][4]) {
    const uint32_t rlo  = (uint32_t)(lane & 15);
    const uint32_t hi16 = (uint32_t)(lane >> 4) * 16;
    uint32_t ah[2][4];
#pragma unroll
    for (int mt = 0; mt < 2; mt++)
        ldm_x4(ah[mt], sb + SXE + (wm * 32 + mt * 16 + rlo) * 32 + hi16);
    uint32_t bf[4][4];
#pragma unroll
    for (int pr = 0; pr < 4; pr++)
        ldm_x4(bf[pr], sb + SWE + ((wn * 4 + pr) * 16 + rlo) * 32 + hi16);
#pragma unroll
    for (int pr = 0; pr < 4; pr++)
#pragma unroll
        for (int mt = 0; mt < 2; mt++) {
            mma_f16(acc[mt][pr * 2],     ah[mt], bf[pr][0], bf[pr][2]);
            mma_f16(acc[mt][pr * 2 + 1], ah[mt], bf[pr][1], bf[pr][3]);
        }
}

// ---------------------------------------------------------------------------
// DP iteration: out = relu(shift(in)@W2^T + x@W1^T + b1 + b2), dithered W2.
// PDL: ext + B stages pre-sync; A stages post-sync. ext computed FIRST.
// ---------------------------------------------------------------------------
__global__ __launch_bounds__(NTHR, 2) void dp_iter_kernel(int src, int wvar, int iter0) {
    extern __shared__ char smem[];
    const uint32_t sb = smem_u32(smem);
    const int tid = threadIdx.x, lane = tid & 31, wid = tid >> 5;
    const int wm = wid >> 1, wn = wid & 1;
    const int m0 = blockIdx.x * BM;
    const int n0 = blockIdx.y * BN;
    const int ln = blockIdx.z;

    const __half* in  = ln ? (iter0 ? g_up[src] : g_dn[src]) : g_up[src];
    __half*       out = ln ? g_dn[src ^ 1] : g_up[src ^ 1];
    const __half* w2  = g_W2[wvar];
    const int shift = ln ? 1 : -1;
    const int wph = -shift;
    const int aoff = (ln && iter0) ? 2 : 0;   // dn reading wph=+1 baking
    const size_t arow = (size_t)(m0 >> 11) * CHROW + (m0 & (LSEQ - 1)) + 1 + shift;

    if (tid == 0) {
        for (int s = 0; s < NSTAGE; s++) {
            mbar_init(sb + SM_FULL + s * 8, 2);   // A arrive + B arrive
            mbar_init(sb + SM_CONS + s * 8, 8);
        }
        mbar_init(sb + SM_EXTF, 1);
    }
    __syncthreads();
    // weight-side prefetch (independent of predecessor's state writes)
    if (tid == 0) {
        issue_ext(sb, sb + SM_EXTF, g_w2e, m0, n0);
        for (int s = 0; s < NSTAGE; s++)
            issue_B(sb + s * STAGE, sb + SM_FULL + s * 8, w2, n0, s);
    }
    pdl_trigger();
    pdl_sync();
    // state-side prefetch
    if (tid == 0)
        for (int s = 0; s < NSTAGE; s++)
            issue_A(sb + s * STAGE, sb + SM_FULL + s * 8, in, arow, s);

    float acc[2][8][4];
#pragma unroll
    for (int i = 0; i < 2; i++)
#pragma unroll
        for (int j = 0; j < 8; j++)
#pragma unroll
            for (int q = 0; q < 4; q++) acc[i][j][q] = 0.0f;

    // ext first: its data arrives early; removes wait from the tail
    mbar_wait(sb + SM_EXTF, 0);
    compute_ext(sb, lane, wm, wn, acc);

    const bool prod = (wid == 0) && elect_one();
    int buf = 0, par = 0;
#pragma unroll 1
    for (int c = 0; c < 4; c++) {
        mbar_wait(sb + SM_FULL + buf * 8, par);
        compute_stage(sb + buf * STAGE, lane, wm, wn, aoff, acc);
        if (c == 0) {      // only buffer 0 is ever refilled (chunk 3)
            if (elect_one()) mbar_arrive(sb + SM_CONS + buf * 8);
            if (prod) {
                mbar_wait(sb + SM_CONS + buf * 8, par);
                issue_B(sb + buf * STAGE, sb + SM_FULL + buf * 8, w2, n0, 3);
                issue_A(sb + buf * STAGE, sb + SM_FULL + buf * 8, in, arow, 3);
            }
        }
        if (++buf == NSTAGE) { buf = 0; par ^= 1; }
    }

    // epilogue: relu(acc) -> fp16 state, swizzled layout (no global reads)
#pragma unroll
    for (int mt = 0; mt < 2; mt++) {
#pragma unroll
        for (int h = 0; h < 2; h++) {
            int m = m0 + wm * 32 + mt * 16 + (lane >> 2) + h * 8;
            int l = m & (LSEQ - 1);
            size_t rowbase = ((size_t)(m >> 11) * CHROW + l + 1) * 64;
            int ph = ((l + wph) & 7) << 4;
#pragma unroll
            for (int nt = 0; nt < 8; nt++) {
                int n = n0 + wn * 64 + nt * 8 + (lane & 3) * 2;
                __half2 hv;
                hv.x = __float2half(fmaxf(acc[mt][nt][2 * h],     0.0f));
                hv.y = __float2half(fmaxf(acc[mt][nt][2 * h + 1], 0.0f));
                size_t off = (size_t)(n >> 6) * A_CH_ELEMS + rowbase
                           + ((((n & 63) * 2) ^ ph) >> 1);
                *reinterpret_cast<__half2*>(out + off) = hv;
            }
        }
    }
}

// ---------------------------------------------------------------------------
// final: miu = relu(x@W3^T + b3 + 2*b4 + W4a*up[j-1] + W4b*down[j+1])
// 8 stages (up variant 0, down variant 1) + ext first. grid (m_tiles, 2). PDL.
// ---------------------------------------------------------------------------
__global__ __launch_bounds__(NTHR, 2) void final_kernel(float* __restrict__ out,
                                                        int src) {
    extern __shared__ char smem[];
    const uint32_t sb = smem_u32(smem);
    const int tid = threadIdx.x, lane = tid & 31, wid = tid >> 5;
    const int wm = wid >> 1, wn = wid & 1;
    const int m0 = blockIdx.x * BM;
    const int n0 = blockIdx.y * BN;
    const size_t rbase = (size_t)(m0 >> 11) * CHROW + (m0 & (LSEQ - 1)) + 1;
    const size_t arow_up = rbase - 1;
    const size_t arow_dn = rbase + 1;
    const __half* upp = g_up[src];
    const __half* dnp = g_dn[src];

    if (tid == 0) {
        for (int s = 0; s < NSTAGE; s++) {
            mbar_init(sb + SM_FULL + s * 8, 2);
            mbar_init(sb + SM_CONS + s * 8, 8);
        }
        mbar_init(sb + SM_EXTF, 1);
    }
    __syncthreads();
    if (tid == 0) {
        issue_ext(sb, sb + SM_EXTF, g_w4e, m0, n0);
        for (int s = 0; s < NSTAGE; s++)
            issue_B(sb + s * STAGE, sb + SM_FULL + s * 8, g_W4[0], n0, s);
    }
    pdl_trigger();
    pdl_sync();
    if (tid == 0)
        for (int s = 0; s < NSTAGE; s++)
            issue_A(sb + s * STAGE, sb + SM_FULL + s * 8, upp, arow_up, s);

    float acc[2][8][4];
#pragma unroll
    for (int i = 0; i < 2; i++)
#pragma unroll
        for (int j = 0; j < 8; j++)
#pragma unroll
            for (int q = 0; q < 4; q++) acc[i][j][q] = 0.0f;

    mbar_wait(sb + SM_EXTF, 0);
    compute_ext(sb, lane, wm, wn, acc);

    const bool prod = (wid == 0) && elect_one();
    int buf = 0, par = 0;
#pragma unroll 1
    for (int t = 0; t < 8; t++) {
        mbar_wait(sb + SM_FULL + buf * 8, par);
        compute_stage(sb + buf * STAGE, lane, wm, wn, 0, acc);
        if (t < 5) {
            if (elect_one()) mbar_arrive(sb + SM_CONS + buf * 8);
            if (prod) {
                mbar_wait(sb + SM_CONS + buf * 8, par);
                int tn = t + 3;
                int phx = tn >> 2;
                const __half* arr = phx ? dnp : upp;
                size_t sr = phx ? arow_dn : arow_up;
                issue_B(sb + buf * STAGE, sb + SM_FULL + buf * 8, g_W4[phx], n0, tn & 3);
                issue_A(sb + buf * STAGE, sb + SM_FULL + buf * 8, arr, sr, tn & 3);
            }
        }
        if (++buf == NSTAGE) { buf = 0; par ^= 1; }
    }

    // epilogue: relu(acc) -> fp32 out (linear layout)
#pragma unroll
    for (int mt = 0; mt < 2; mt++) {
#pragma unroll
        for (int h = 0; h < 2; h++) {
            int m = m0 + wm * 32 + mt * 16 + (lane >> 2) + h * 8;
            float* orow = out + (size_t)m * DDIM;
#pragma unroll
            for (int nt = 0; nt < 8; nt++) {
                int n = n0 + wn * 64 + nt * 8 + (lane & 3) * 2;
                float2 o = make_float2(fmaxf(acc[mt][nt][2 * h],     0.0f),
                                       fmaxf(acc[mt][nt][2 * h + 1], 0.0f));
                *reinterpret_cast<float2*>(orow + n) = o;
            }
        }
    }
}

// ---------------------------------------------------------------------------
extern "C" void kernel_launch(void* const* d_in, const int* in_sizes, int n_in,
                              void* d_out, int out_size) {
    const float* x  = (const float*)d_in[0];
    const float* W1 = (const float*)d_in[1];
    const float* b1 = (const float*)d_in[2];
    const float* W2 = (const float*)d_in[3];
    const float* b2 = (const float*)d_in[4];
    const float* W3 = (const float*)d_in[5];
    const float* b3 = (const float*)d_in[6];
    const float* W4 = (const float*)d_in[7];
    const float* b4 = (const float*)d_in[8];
    float* out = (float*)d_out;

    cudaFuncSetAttribute(dp_iter_kernel, cudaFuncAttributeMaxDynamicSharedMemorySize, SMEM_BYTES);
    cudaFuncSetAttribute(final_kernel,   cudaFuncAttributeMaxDynamicSharedMemorySize, SMEM_BYTES);

    // weight/x prep first, then state prep (so dp_iter #1's pre-sync weight
    // prefetch only touches data finished before prep started -> PDL-safe)
    xext_kernel<<<(MTOT + 255) / 256, 256>>>(x);
    split_w_kernel<<<(DDIM * DDIM + 255) / 256, 256>>>(W2, W4, W1, b1, b2, W3, b3, b4);
    prep_kernel<<<(MTOT * (DDIM / 2) + 255) / 256, 256>>>(x, W1, b1, b2);

    cudaLaunchAttribute attrs[1];
    attrs[0].id = cudaLaunchAttributeProgrammaticStreamSerialization;
    attrs[0].val.programmaticStreamSerializationAllowed = 1;

    int src = 0;
    for (int t = 0; t < 7; t++) {
        cudaLaunchConfig_t cfg = {};
        cfg.gridDim = dim3(MTOT / BM, 2, 2);
        cfg.blockDim = dim3(NTHR, 1, 1);
        cfg.dynamicSmemBytes = SMEM_BYTES;
        cfg.stream = 0;
        cfg.attrs = attrs;
        cfg.numAttrs = 1;
        cudaLaunchKernelEx(&cfg, dp_iter_kernel, src, t & 1, (t == 0) ? 1 : 0);
        src ^= 1;
    }
    {
        cudaLaunchConfig_t cfg = {};
        cfg.gridDim = dim3(MTOT / BM, 2);
        cfg.blockDim = dim3(NTHR, 1, 1);
        cfg.dynamicSmemBytes = SMEM_BYTES;
        cfg.stream = 0;
        cfg.attrs = attrs;
        cfg.numAttrs = 1;
        cudaLaunchKernelEx(&cfg, final_kernel, out, src);
    }
}

// round 17
// speedup vs baseline: 1.6013x; 1.0055x over previous
#include <cuda_runtime.h>
#include <cuda_fp16.h>
#include <cstdint>

#define BSZ   16
#define LSEQ  2048
#define DDIM  256
#define MTOT  (BSZ * LSEQ)    // 32768
#define BM    128
#define BN    128
#define NTHR  256

// A (state): single fp16, 4 chunks of k64; row = 64 fp16 = 128B, SW128 phase
// baked per (l + wph). B (weights): single fp16, 4 chunks of k64, phase (n&7),
// TWO complementary-rounded variants alternated across iterations (dither).
// ext: k16 tail computing a = x@W1^T + bias exactly via hi/lo cross terms.
// Iter-1 dn lane reads g_up[0] (wph=+1 baking) with A-swizzle lane offset +2.
#define CHROW  2056
#define A_CH_ELEMS ((size_t)BSZ * CHROW * 64)   // per k64 chunk
#define W_CH   (256 * 64)

// ---------------- global state (static .bss; pad rows stay zero) ----------
__device__ __align__(128) __half g_up[2][4 * A_CH_ELEMS];
__device__ __align__(128) __half g_dn[2][4 * A_CH_ELEMS];
__device__ __align__(128) __half g_W2[2][4 * W_CH];   // [variant][chunk...]
__device__ __align__(128) __half g_W4[2][4 * W_CH];
__device__ __align__(128) __half g_xe[(size_t)MTOT * 16];
__device__ __align__(128) __half g_w2e[256 * 16];
__device__ __align__(128) __half g_w4e[256 * 16];

// ---------------- helpers ----------------
__device__ __forceinline__ uint32_t smem_u32(const void* p) {
    uint32_t a;
    asm("{ .reg .u64 t; cvta.to.shared.u64 t, %1; cvt.u32.u64 %0, t; }" : "=r"(a) : "l"(p));
    return a;
}
__device__ __forceinline__ uint32_t elect_one() {
    uint32_t pred;
    asm volatile("{\n\t.reg .pred p;\n\telect.sync _|p, 0xFFFFFFFF;\n\t"
                 "selp.b32 %0, 1, 0, p;\n\t}" : "=r"(pred));
    return pred;
}
__device__ __forceinline__ void ldm_x4(uint32_t* r, uint32_t addr) {
    asm volatile("ldmatrix.sync.aligned.m8n8.x4.shared.b16 {%0,%1,%2,%3}, [%4];"
                 : "=r"(r[0]), "=r"(r[1]), "=r"(r[2]), "=r"(r[3]) : "r"(addr));
}
__device__ __forceinline__ void mma_f16(float* c, const uint32_t* a, uint32_t b0, uint32_t b1) {
    asm volatile("mma.sync.aligned.m16n8k16.row.col.f32.f16.f16.f32 "
                 "{%0,%1,%2,%3}, {%4,%5,%6,%7}, {%8,%9}, {%0,%1,%2,%3};"
                 : "+f"(c[0]), "+f"(c[1]), "+f"(c[2]), "+f"(c[3])
                 : "r"(a[0]), "r"(a[1]), "r"(a[2]), "r"(a[3]), "r"(b0), "r"(b1));
}
__device__ __forceinline__ void bulk_g2s(uint32_t sdst, const void* gsrc,
                                         uint32_t bytes, uint32_t mbar) {
    asm volatile(
        "cp.async.bulk.shared::cluster.global.mbarrier::complete_tx::bytes [%0], [%1], %2, [%3];"
        :: "r"(sdst), "l"(gsrc), "r"(bytes), "r"(mbar) : "memory");
}
__device__ __forceinline__ void mbar_init(uint32_t mbar, uint32_t cnt) {
    asm volatile("mbarrier.init.shared.b64 [%0], %1;" :: "r"(mbar), "r"(cnt) : "memory");
}
__device__ __forceinline__ void mbar_expect_tx(uint32_t mbar, uint32_t bytes) {
    asm volatile("mbarrier.arrive.expect_tx.shared.b64 _, [%0], %1;"
                 :: "r"(mbar), "r"(bytes) : "memory");
}
__device__ __forceinline__ void mbar_arrive(uint32_t mbar) {
    asm volatile("mbarrier.arrive.release.cta.shared::cta.b64 _, [%0];"
                 :: "r"(mbar) : "memory");
}
__device__ __forceinline__ void mbar_wait(uint32_t mbar, uint32_t parity) {
    uint32_t done;
    asm volatile(
        "{\n\t.reg .pred p;\n\t"
        "mbarrier.try_wait.parity.acquire.cta.shared::cta.b64 p, [%1], %2;\n\t"
        "selp.b32 %0, 1, 0, p;\n\t}"
        : "=r"(done) : "r"(mbar), "r"(parity) : "memory");
    if (!done) {
        asm volatile(
            "{\n\t.reg .pred P1;\n\t"
            "W_%=:\n\t"
            "mbarrier.try_wait.parity.acquire.cta.shared::cta.b64 P1, [%0], %1, 0x989680;\n\t"
            "@P1 bra.uni D_%=;\n\t"
            "bra.uni W_%=;\n\t"
            "D_%=:\n\t}"
            :: "r"(mbar), "r"(parity) : "memory");
    }
}
__device__ __forceinline__ void pdl_trigger() {
#if defined(__CUDA_ARCH__) && __CUDA_ARCH__ >= 900
    cudaTriggerProgrammaticLaunchCompletion();
#endif
}
__device__ __forceinline__ void pdl_sync() {
#if defined(__CUDA_ARCH__) && __CUDA_ARCH__ >= 900
    cudaGridDependencySynchronize();
#endif
}

// ---------------- SMEM layout ----------------
static constexpr int SA      = 0;
static constexpr int SB      = 16384;
static constexpr int STAGE   = 32768;
static constexpr int NSTAGE  = 3;
static constexpr int SXE     = NSTAGE * STAGE;            // 98304, A ext 4KB
static constexpr int SWE     = SXE + 4096;                // B ext 4KB
static constexpr int SM_FULL = SWE + 4096;                // 106496
static constexpr int SM_CONS = SM_FULL + NSTAGE * 8;
static constexpr int SM_EXTF = SM_CONS + NSTAGE * 8;
static constexpr int SMEM_BYTES = SM_EXTF + 8;

// state element index (fp16 units) for (m, n), write-phase wph
__device__ __forceinline__ size_t st_idx(int m, int n, int wph) {
    int l = m & (LSEQ - 1);
    size_t row = (size_t)(m >> 11) * CHROW + l + 1;
    int ph  = ((l + wph) & 7) << 4;
    int raw = (n & 63) * 2;
    return (size_t)(n >> 6) * A_CH_ELEMS + row * 64 + ((raw ^ ph) >> 1);
}

// complementary fp16 rounding pair
__device__ __forceinline__ void round_pair(float w, __half& ha, __half& hb) {
    ha = __float2half(w);
    hb = __float2half(w + (w - __half2float(ha)));   // opposite-side neighbor
}

// ---------------------------------------------------------------------------
// prep: state#1 = relu(x@W1^T + b1 + b2) -> g_up[0] ONLY (wph=+1 baking).
// Iter-1 dn lane reads this array with A-swizzle offset +2.
// Early pdl_trigger: dp_iter #1's pre-sync weight prefetch overlaps this.
// ---------------------------------------------------------------------------
__global__ void prep_kernel(const float* __restrict__ x,
                            const float* __restrict__ W1,
                            const float* __restrict__ b1,
                            const float* __restrict__ b2) {
    pdl_trigger();
    int idx = blockIdx.x * blockDim.x + threadIdx.x;
    if (idx >= MTOT * (DDIM / 2)) return;
    int n = (idx & 127) * 2;
    int m = idx >> 7;
    int b = m / LSEQ;
    int l = m & (LSEQ - 1);
    const float* xp = x + (size_t)b * 4 * LSEQ + l;
    float xv[4];
#pragma unroll
    for (int dd = 0; dd < 4; dd++) xv[dd] = xp[dd * LSEQ];
    float s0 = b1[n]     + b2[n];
    float s1 = b1[n + 1] + b2[n + 1];
#pragma unroll
    for (int dd = 0; dd < 4; dd++) {
        s0 = fmaf(xv[dd], W1[n * 4 + dd],       s0);
        s1 = fmaf(xv[dd], W1[(n + 1) * 4 + dd], s1);
    }
    __half2 hv;
    hv.x = __float2half(fmaxf(s0, 0.0f));
    hv.y = __float2half(fmaxf(s1, 0.0f));
    *reinterpret_cast<__half2*>(&g_up[0][st_idx(m, n, +1)]) = hv;
}

// ---------------------------------------------------------------------------
// fused weight/x prologue: dithered W2/W4 split + ext rows + x_ext rows.
// 65536 threads; first 32768 also build their x_ext row.
// ---------------------------------------------------------------------------
__global__ void split_w_kernel(const float* __restrict__ x,
                               const float* __restrict__ W2,
                               const float* __restrict__ W4,
                               const float* __restrict__ W1,
                               const float* __restrict__ b1,
                               const float* __restrict__ b2,
                               const float* __restrict__ W3,
                               const float* __restrict__ b3,
                               const float* __restrict__ b4) {
    int idx = blockIdx.x * blockDim.x + threadIdx.x;   // (n, k)
    if (idx >= DDIM * DDIM) return;

    // ---- x_ext rows: [xh(4), xh(4), xl(4), 1, 1, 0, 0] (first MTOT threads)
    if (idx < MTOT) {
        int m = idx;
        int b = m >> 11, l = m & (LSEQ - 1);
        __half r[16];
#pragma unroll
        for (int j = 0; j < 16; j++) r[j] = __float2half(0.0f);
#pragma unroll
        for (int dd = 0; dd < 4; dd++) {
            float xv = x[(size_t)b * 4 * LSEQ + dd * LSEQ + l];
            __half xh = __float2half(xv);
            r[dd]     = xh;
            r[4 + dd] = xh;
            r[8 + dd] = __float2half(xv - __half2float(xh));
        }
        r[12] = __float2half(1.0f);
        r[13] = __float2half(1.0f);
        uint4* dst = reinterpret_cast<uint4*>(g_xe + (size_t)m * 16);
        dst[0] = reinterpret_cast<const uint4*>(r)[0];
        dst[1] = reinterpret_cast<const uint4*>(r)[1];
    }

    // ---- dithered weight split
    int n = idx >> 8, k = idx & 255;
    int ph = (n & 7) << 4;
    size_t off = (size_t)(k >> 6) * W_CH + (size_t)n * 64 + ((((k & 63) * 2)) ^ ph) / 2;
    __half ha, hb;
    round_pair(W2[idx], ha, hb);
    g_W2[0][off] = ha;
    g_W2[1][off] = hb;
    round_pair(W4[idx], ha, hb);
    g_W4[0][off] = ha;
    g_W4[1][off] = hb;

    // ---- weight-ext rows: [wh(4), wl(4), wh(4), bias_hi, bias_lo, 0, 0]
    if (k == 0) {
        __half r2[16], r4[16];
#pragma unroll
        for (int j = 0; j < 16; j++) { r2[j] = __float2half(0.0f); r4[j] = r2[j]; }
#pragma unroll
        for (int dd = 0; dd < 4; dd++) {
            float w1v = W1[n * 4 + dd];
            __half w1h = __float2half(w1v);
            r2[dd]     = w1h;
            r2[4 + dd] = __float2half(w1v - __half2float(w1h));
            r2[8 + dd] = w1h;
            float w3v = W3[n * 4 + dd];
            __half w3h = __float2half(w3v);
            r4[dd]     = w3h;
            r4[4 + dd] = __float2half(w3v - __half2float(w3h));
            r4[8 + dd] = w3h;
        }
        float bias2 = b1[n] + b2[n];
        __half b2h = __float2half(bias2);
        r2[12] = b2h;
        r2[13] = __float2half(bias2 - __half2float(b2h));
        float bias4 = b3[n] + 2.0f * b4[n];
        __half b4h = __float2half(bias4);
        r4[12] = b4h;
        r4[13] = __float2half(bias4 - __half2float(b4h));
        uint4* d2 = reinterpret_cast<uint4*>(g_w2e + (size_t)n * 16);
        uint4* d4 = reinterpret_cast<uint4*>(g_w4e + (size_t)n * 16);
        d2[0] = reinterpret_cast<const uint4*>(r2)[0];
        d2[1] = reinterpret_cast<const uint4*>(r2)[1];
        d4[0] = reinterpret_cast<const uint4*>(r4)[0];
        d4[1] = reinterpret_cast<const uint4*>(r4)[1];
    }
}

// split A/B prefetch: each expect_tx is one arrival; stage barriers count=2.
__device__ __forceinline__ void issue_B(uint32_t sbase, uint32_t mbar,
                                        const __half* w, int n0, int c) {
    mbar_expect_tx(mbar, 16384);
    bulk_g2s(sbase + SB, w + (size_t)c * W_CH + (size_t)n0 * 64, 16384, mbar);
}
__device__ __forceinline__ void issue_A(uint32_t sbase, uint32_t mbar,
                                        const __half* in, size_t arow, int c) {
    mbar_expect_tx(mbar, 16384);
    bulk_g2s(sbase + SA, in + (size_t)c * A_CH_ELEMS + arow * 64, 16384, mbar);
}
// ext pair: x rows + weight-ext rows (4KB each), one expect (count=1)
__device__ __forceinline__ void issue_ext(uint32_t sb, uint32_t mbar,
                                          const __half* we, int m0, int n0) {
    mbar_expect_tx(mbar, 8192);
    bulk_g2s(sb + SXE, g_xe + (size_t)m0 * 16, 4096, mbar);
    bulk_g2s(sb + SWE, we + (size_t)n0 * 16, 4096, mbar);
}

// compute one k64 stage, single-pass fp16. warp tile 32x64.
// aoff = A-tile swizzle lane offset (0 normally; 2 for iter-1 dn lane).
__device__ __forceinline__ void compute_stage(uint32_t base, int lane, int wm, int wn,
                                              int aoff, float acc[2][8][4]) {
    const uint32_t swzA = (uint32_t)((lane + aoff) & 7) << 4;
    const uint32_t swzB = (uint32_t)(lane & 7) << 4;
    const uint32_t rlo  = (uint32_t)(lane & 15);
    const uint32_t hi16 = (uint32_t)(lane >> 4) * 16;
#pragma unroll
    for (int ks = 0; ks < 4; ks++) {
        uint32_t cbase = (uint32_t)(ks * 32) + hi16;
        uint32_t chA = cbase ^ swzA;
        uint32_t chB = cbase ^ swzB;
        uint32_t ah[2][4];
#pragma unroll
        for (int mt = 0; mt < 2; mt++)
            ldm_x4(ah[mt], base + SA + (wm * 32 + mt * 16 + rlo) * 128 + chA);
        uint32_t bf[4][4];
#pragma unroll
        for (int pr = 0; pr < 4; pr++)
            ldm_x4(bf[pr], base + SB + ((wn * 4 + pr) * 16 + rlo) * 128 + chB);
#pragma unroll
        for (int pr = 0; pr < 4; pr++)
#pragma unroll
            for (int mt = 0; mt < 2; mt++) {
                mma_f16(acc[mt][pr * 2],     ah[mt], bf[pr][0], bf[pr][2]);
                mma_f16(acc[mt][pr * 2 + 1], ah[mt], bf[pr][1], bf[pr][3]);
            }
    }
}

// ext k16 step: rows of 32B, unswizzled
__device__ __forceinline__ void compute_ext(uint32_t sb, int lane, int wm, int wn,
                                            float acc[2][8][4]) {
    const uint32_t rlo  = (uint32_t)(lane & 15);
    const uint32_t hi16 = (uint32_t)(lane >> 4) * 16;
    uint32_t ah[2][4];
#pragma unroll
    for (int mt = 0; mt < 2; mt++)
        ldm_x4(ah[mt], sb + SXE + (wm * 32 + mt * 16 + rlo) * 32 + hi16);
    uint32_t bf[4][4];
#pragma unroll
    for (int pr = 0; pr < 4; pr++)
        ldm_x4(bf[pr], sb + SWE + ((wn * 4 + pr) * 16 + rlo) * 32 + hi16);
#pragma unroll
    for (int pr = 0; pr < 4; pr++)
#pragma unroll
        for (int mt = 0; mt < 2; mt++) {
            mma_f16(acc[mt][pr * 2],     ah[mt], bf[pr][0], bf[pr][2]);
            mma_f16(acc[mt][pr * 2 + 1], ah[mt], bf[pr][1], bf[pr][3]);
        }
}

// ---------------------------------------------------------------------------
// DP iteration: out = relu(shift(in)@W2^T + x@W1^T + b1 + b2), dithered W2.
// PDL: ext + B stages pre-sync; A stages post-sync. ext computed FIRST.
// ---------------------------------------------------------------------------
__global__ __launch_bounds__(NTHR, 2) void dp_iter_kernel(int src, int wvar, int iter0) {
    extern __shared__ char smem[];
    const uint32_t sb = smem_u32(smem);
    const int tid = threadIdx.x, lane = tid & 31, wid = tid >> 5;
    const int wm = wid >> 1, wn = wid & 1;
    const int m0 = blockIdx.x * BM;
    const int n0 = blockIdx.y * BN;
    const int ln = blockIdx.z;

    const __half* in  = ln ? (iter0 ? g_up[src] : g_dn[src]) : g_up[src];
    __half*       out = ln ? g_dn[src ^ 1] : g_up[src ^ 1];
    const __half* w2  = g_W2[wvar];
    const int shift = ln ? 1 : -1;
    const int wph = -shift;
    const int aoff = (ln && iter0) ? 2 : 0;   // dn reading wph=+1 baking
    const size_t arow = (size_t)(m0 >> 11) * CHROW + (m0 & (LSEQ - 1)) + 1 + shift;

    if (tid == 0) {
        for (int s = 0; s < NSTAGE; s++) {
            mbar_init(sb + SM_FULL + s * 8, 2);   // A arrive + B arrive
            mbar_init(sb + SM_CONS + s * 8, 8);
        }
        mbar_init(sb + SM_EXTF, 1);
    }
    __syncthreads();
    // weight-side prefetch (independent of predecessor's state writes)
    if (tid == 0) {
        issue_ext(sb, sb + SM_EXTF, g_w2e, m0, n0);
        for (int s = 0; s < NSTAGE; s++)
            issue_B(sb + s * STAGE, sb + SM_FULL + s * 8, w2, n0, s);
    }
    pdl_trigger();
    pdl_sync();
    // state-side prefetch
    if (tid == 0)
        for (int s = 0; s < NSTAGE; s++)
            issue_A(sb + s * STAGE, sb + SM_FULL + s * 8, in, arow, s);

    float acc[2][8][4];
#pragma unroll
    for (int i = 0; i < 2; i++)
#pragma unroll
        for (int j = 0; j < 8; j++)
#pragma unroll
            for (int q = 0; q < 4; q++) acc[i][j][q] = 0.0f;

    // ext first: its data arrives early; removes wait from the tail
    mbar_wait(sb + SM_EXTF, 0);
    compute_ext(sb, lane, wm, wn, acc);

    const bool prod = (wid == 0) && elect_one();
    int buf = 0, par = 0;
#pragma unroll 1
    for (int c = 0; c < 4; c++) {
        mbar_wait(sb + SM_FULL + buf * 8, par);
        compute_stage(sb + buf * STAGE, lane, wm, wn, aoff, acc);
        if (c == 0) {      // only buffer 0 is ever refilled (chunk 3)
            if (elect_one()) mbar_arrive(sb + SM_CONS + buf * 8);
            if (prod) {
                mbar_wait(sb + SM_CONS + buf * 8, par);
                issue_B(sb + buf * STAGE, sb + SM_FULL + buf * 8, w2, n0, 3);
                issue_A(sb + buf * STAGE, sb + SM_FULL + buf * 8, in, arow, 3);
            }
        }
        if (++buf == NSTAGE) { buf = 0; par ^= 1; }
    }

    // epilogue: relu(acc) -> fp16 state, swizzled layout (no global reads)
#pragma unroll
    for (int mt = 0; mt < 2; mt++) {
#pragma unroll
        for (int h = 0; h < 2; h++) {
            int m = m0 + wm * 32 + mt * 16 + (lane >> 2) + h * 8;
            int l = m & (LSEQ - 1);
            size_t rowbase = ((size_t)(m >> 11) * CHROW + l + 1) * 64;
            int ph = ((l + wph) & 7) << 4;
#pragma unroll
            for (int nt = 0; nt < 8; nt++) {
                int n = n0 + wn * 64 + nt * 8 + (lane & 3) * 2;
                __half2 hv;
                hv.x = __float2half(fmaxf(acc[mt][nt][2 * h],     0.0f));
                hv.y = __float2half(fmaxf(acc[mt][nt][2 * h + 1], 0.0f));
                size_t off = (size_t)(n >> 6) * A_CH_ELEMS + rowbase
                           + ((((n & 63) * 2) ^ ph) >> 1);
                *reinterpret_cast<__half2*>(out + off) = hv;
            }
        }
    }
}

// ---------------------------------------------------------------------------
// final: miu = relu(x@W3^T + b3 + 2*b4 + W4a*up[j-1] + W4b*down[j+1])
// 8 stages (up variant 0, down variant 1) + ext first. grid (m_tiles, 2). PDL.
// ---------------------------------------------------------------------------
__global__ __launch_bounds__(NTHR, 2) void final_kernel(float* __restrict__ out,
                                                        int src) {
    extern __shared__ char smem[];
    const uint32_t sb = smem_u32(smem);
    const int tid = threadIdx.x, lane = tid & 31, wid = tid >> 5;
    const int wm = wid >> 1, wn = wid & 1;
    const int m0 = blockIdx.x * BM;
    const int n0 = blockIdx.y * BN;
    const size_t rbase = (size_t)(m0 >> 11) * CHROW + (m0 & (LSEQ - 1)) + 1;
    const size_t arow_up = rbase - 1;
    const size_t arow_dn = rbase + 1;
    const __half* upp = g_up[src];
    const __half* dnp = g_dn[src];

    if (tid == 0) {
        for (int s = 0; s < NSTAGE; s++) {
            mbar_init(sb + SM_FULL + s * 8, 2);
            mbar_init(sb + SM_CONS + s * 8, 8);
        }
        mbar_init(sb + SM_EXTF, 1);
    }
    __syncthreads();
    if (tid == 0) {
        issue_ext(sb, sb + SM_EXTF, g_w4e, m0, n0);
        for (int s = 0; s < NSTAGE; s++)
            issue_B(sb + s * STAGE, sb + SM_FULL + s * 8, g_W4[0], n0, s);
    }
    pdl_trigger();
    pdl_sync();
    if (tid == 0)
        for (int s = 0; s < NSTAGE; s++)
            issue_A(sb + s * STAGE, sb + SM_FULL + s * 8, upp, arow_up, s);

    float acc[2][8][4];
#pragma unroll
    for (int i = 0; i < 2; i++)
#pragma unroll
        for (int j = 0; j < 8; j++)
#pragma unroll
            for (int q = 0; q < 4; q++) acc[i][j][q] = 0.0f;

    mbar_wait(sb + SM_EXTF, 0);
    compute_ext(sb, lane, wm, wn, acc);

    const bool prod = (wid == 0) && elect_one();
    int buf = 0, par = 0;
#pragma unroll 1
    for (int t = 0; t < 8; t++) {
        mbar_wait(sb + SM_FULL + buf * 8, par);
        compute_stage(sb + buf * STAGE, lane, wm, wn, 0, acc);
        if (t < 5) {
            if (elect_one()) mbar_arrive(sb + SM_CONS + buf * 8);
            if (prod) {
                mbar_wait(sb + SM_CONS + buf * 8, par);
                int tn = t + 3;
                int phx = tn >> 2;
                const __half* arr = phx ? dnp : upp;
                size_t sr = phx ? arow_dn : arow_up;
                issue_B(sb + buf * STAGE, sb + SM_FULL + buf * 8, g_W4[phx], n0, tn & 3);
                issue_A(sb + buf * STAGE, sb + SM_FULL + buf * 8, arr, sr, tn & 3);
            }
        }
        if (++buf == NSTAGE) { buf = 0; par ^= 1; }
    }

    // epilogue: relu(acc) -> fp32 out (linear layout)
#pragma unroll
    for (int mt = 0; mt < 2; mt++) {
#pragma unroll
        for (int h = 0; h < 2; h++) {
            int m = m0 + wm * 32 + mt * 16 + (lane >> 2) + h * 8;
            float* orow = out + (size_t)m * DDIM;
#pragma unroll
            for (int nt = 0; nt < 8; nt++) {
                int n = n0 + wn * 64 + nt * 8 + (lane & 3) * 2;
                float2 o = make_float2(fmaxf(acc[mt][nt][2 * h],     0.0f),
                                       fmaxf(acc[mt][nt][2 * h + 1], 0.0f));
                *reinterpret_cast<float2*>(orow + n) = o;
            }
        }
    }
}

// ---------------------------------------------------------------------------
extern "C" void kernel_launch(void* const* d_in, const int* in_sizes, int n_in,
                              void* d_out, int out_size) {
    const float* x  = (const float*)d_in[0];
    const float* W1 = (const float*)d_in[1];
    const float* b1 = (const float*)d_in[2];
    const float* W2 = (const float*)d_in[3];
    const float* b2 = (const float*)d_in[4];
    const float* W3 = (const float*)d_in[5];
    const float* b3 = (const float*)d_in[6];
    const float* W4 = (const float*)d_in[7];
    const float* b4 = (const float*)d_in[8];
    float* out = (float*)d_out;

    cudaFuncSetAttribute(dp_iter_kernel, cudaFuncAttributeMaxDynamicSharedMemorySize, SMEM_BYTES);
    cudaFuncSetAttribute(final_kernel,   cudaFuncAttributeMaxDynamicSharedMemorySize, SMEM_BYTES);

    // fused weight/x prologue first, then state prep (dp_iter #1's pre-sync
    // weight prefetch only touches data finished before prep started).
    split_w_kernel<<<(DDIM * DDIM + 255) / 256, 256>>>(x, W2, W4, W1, b1, b2, W3, b3, b4);
    prep_kernel<<<(MTOT * (DDIM / 2) + 255) / 256, 256>>>(x, W1, b1, b2);

    cudaLaunchAttribute attrs[1];
    attrs[0].id = cudaLaunchAttributeProgrammaticStreamSerialization;
    attrs[0].val.programmaticStreamSerializationAllowed = 1;

    int src = 0;
    for (int t = 0; t < 7; t++) {
        cudaLaunchConfig_t cfg = {};
        cfg.gridDim = dim3(MTOT / BM, 2, 2);
        cfg.blockDim = dim3(NTHR, 1, 1);
        cfg.dynamicSmemBytes = SMEM_BYTES;
        cfg.stream = 0;
        cfg.attrs = attrs;
        cfg.numAttrs = 1;
        cudaLaunchKernelEx(&cfg, dp_iter_kernel, src, t & 1, (t == 0) ? 1 : 0);
        src ^= 1;
    }
    {
        cudaLaunchConfig_t cfg = {};
        cfg.gridDim = dim3(MTOT / BM, 2);
        cfg.blockDim = dim3(NTHR, 1, 1);
        cfg.dynamicSmemBytes = SMEM_BYTES;
        cfg.stream = 0;
        cfg.attrs = attrs;
        cfg.numAttrs = 1;
        cudaLaunchKernelEx(&cfg, final_kernel, out, src);
    }
}